// round 1
// baseline (speedup 1.0000x reference)
#include <cuda_runtime.h>

#define NN 100000
#define NE 1600000
#define NL 200000
#define DIN 128
#define DH  128
#define DOUT 64

// ---------------- scratch (device globals; no allocation allowed) ----------
__device__ __align__(16) int   g_deg[NN];
__device__ __align__(16) float g_dinv[NN];
__device__ __align__(16) float g_invdeg[NN];
__device__ __align__(16) int   g_off[NN + 1];
__device__ __align__(16) int   g_cursor[NN];
__device__ __align__(16) int   g_csr[NE];
__device__ __align__(16) int   g_bsum[128];
__device__ __align__(16) float g_h1[(size_t)NN * DH];
__device__ __align__(16) float g_z [(size_t)NN * DH];
__device__ __align__(16) float g_h2[(size_t)NN * DOUT];
__device__ __align__(16) float g_z2[(size_t)NN * DOUT];

// ---------------- setup kernels --------------------------------------------
__global__ void k_zero_deg() {
    int i = blockIdx.x * blockDim.x + threadIdx.x;
    if (i < NN) g_deg[i] = 0;
}

__global__ void k_degree(const int* __restrict__ ei) {
    int e = blockIdx.x * blockDim.x + threadIdx.x;
    if (e < NE) atomicAdd(&g_deg[ei[NE + e]], 1);
}

__global__ void k_dinv() {
    int i = blockIdx.x * blockDim.x + threadIdx.x;
    if (i < NN) {
        float d = (float)(g_deg[i] + 1);
        g_dinv[i]   = rsqrtf(d);
        g_invdeg[i] = 1.0f / d;
    }
}

// exclusive scan of g_deg -> g_off, 3-phase
__global__ void k_scan1(int n) {
    __shared__ int wsum[32];
    int t   = threadIdx.x;
    int gid = blockIdx.x * 1024 + t;
    int v = (gid < n) ? g_deg[gid] : 0;
    int x = v;
    #pragma unroll
    for (int o = 1; o < 32; o <<= 1) {
        int y = __shfl_up_sync(0xffffffffu, x, o);
        if ((t & 31) >= o) x += y;
    }
    if ((t & 31) == 31) wsum[t >> 5] = x;
    __syncthreads();
    if (t < 32) {
        int w = wsum[t];
        int xx = w;
        #pragma unroll
        for (int o = 1; o < 32; o <<= 1) {
            int y = __shfl_up_sync(0xffffffffu, xx, o);
            if (t >= o) xx += y;
        }
        wsum[t] = xx - w;  // exclusive warp prefix
    }
    __syncthreads();
    int excl = x - v + wsum[t >> 5];
    if (gid < n) g_off[gid] = excl;
    if (t == 1023) g_bsum[blockIdx.x] = excl + v;  // block total
}

__global__ void k_scan2(int nb) {
    __shared__ int s[128];
    int t = threadIdx.x;
    int v = (t < nb) ? g_bsum[t] : 0;
    s[t] = v;
    __syncthreads();
    for (int o = 1; o < 128; o <<= 1) {
        int x = (t >= o) ? s[t - o] : 0;
        __syncthreads();
        s[t] += x;
        __syncthreads();
    }
    if (t < nb) g_bsum[t] = s[t] - v;  // exclusive
}

__global__ void k_scan3(int n) {
    int t = threadIdx.x;
    int gid = blockIdx.x * 1024 + t;
    if (gid < n) {
        int v = g_off[gid] + g_bsum[blockIdx.x];
        g_off[gid]    = v;
        g_cursor[gid] = v;
    }
    if (gid == 0) g_off[n] = NE;
}

__global__ void k_scatter(const int* __restrict__ ei) {
    int e = blockIdx.x * blockDim.x + threadIdx.x;
    if (e < NE) {
        int s = ei[e];
        int d = ei[NE + e];
        int p = atomicAdd(&g_cursor[d], 1);
        g_csr[p] = s;
    }
}

// ---------------- SGEMM: C[M,BN] = A[M,128] @ B[128,BN] --------------------
template <int BN>
__global__ void k_gemm(const float* __restrict__ A, const float* __restrict__ B,
                       float* __restrict__ C, int M) {
    const int BM = 128, BK = 8, K = 128;
    const int TN = BN / 16;   // 8 for BN=128, 4 for BN=64
    __shared__ float As[BK][BM + 4];
    __shared__ float Bs[BK][BN];
    int tid = threadIdx.x;          // 256 threads
    int ty  = tid / 16, tx = tid % 16;
    int row0 = blockIdx.x * BM;

    float acc[8][TN];
    #pragma unroll
    for (int i = 0; i < 8; i++)
        #pragma unroll
        for (int j = 0; j < TN; j++) acc[i][j] = 0.0f;

    for (int k0 = 0; k0 < K; k0 += BK) {
        // A tile: 128 rows x 8 k
        #pragma unroll
        for (int i = 0; i < 4; i++) {
            int id = tid + i * 256;
            int r  = id >> 3, kk = id & 7;
            int row = row0 + r;
            As[kk][r] = (row < M) ? A[(long)row * K + k0 + kk] : 0.0f;
        }
        // B tile: 8 x BN
        #pragma unroll
        for (int i = 0; i < (BK * BN) / 256; i++) {
            int id = tid + i * 256;
            int kk = id / BN, c = id % BN;
            Bs[kk][c] = B[(long)(k0 + kk) * BN + c];
        }
        __syncthreads();
        #pragma unroll
        for (int kk = 0; kk < BK; kk++) {
            float ra[8], rb[TN];
            #pragma unroll
            for (int i = 0; i < 8; i++) ra[i] = As[kk][ty * 8 + i];
            #pragma unroll
            for (int j = 0; j < TN; j++) rb[j] = Bs[kk][tx * TN + j];
            #pragma unroll
            for (int i = 0; i < 8; i++)
                #pragma unroll
                for (int j = 0; j < TN; j++) acc[i][j] += ra[i] * rb[j];
        }
        __syncthreads();
    }

    #pragma unroll
    for (int i = 0; i < 8; i++) {
        int row = row0 + ty * 8 + i;
        if (row >= M) continue;
        float* cp = C + (long)row * BN + tx * TN;
        #pragma unroll
        for (int j = 0; j < TN; j += 4) {
            float4 v = make_float4(acc[i][j], acc[i][j + 1], acc[i][j + 2], acc[i][j + 3]);
            *(float4*)(cp + j) = v;
        }
    }
}

// ---------------- aggregation: one warp per node ---------------------------
template <int D, bool RELU>
__global__ void k_agg(const float* __restrict__ h, const float* __restrict__ bias,
                      float* __restrict__ zo) {
    int w    = (blockIdx.x * blockDim.x + threadIdx.x) >> 5;
    int lane = threadIdx.x & 31;
    if (w >= NN) return;
    const int V = D / 32;  // 4 (D=128) or 2 (D=64)
    int beg = g_off[w], end = g_off[w + 1];
    float di = g_dinv[w];
    float acc[V];
    #pragma unroll
    for (int i = 0; i < V; i++) acc[i] = 0.0f;

    for (int base = beg; base < end; base += 32) {
        int e = base + lane;
        int s = 0; float nm = 0.0f;
        if (e < end) { s = g_csr[e]; nm = g_dinv[s] * di; }
        int cnt = min(32, end - base);
        for (int j = 0; j < cnt; j++) {
            int ss   = __shfl_sync(0xffffffffu, s, j);
            float nn = __shfl_sync(0xffffffffu, nm, j);
            const float* hp = h + (size_t)ss * D + lane * V;
            if (V == 4) {
                float4 v = *(const float4*)hp;
                acc[0] += v.x * nn; acc[1] += v.y * nn;
                acc[2] += v.z * nn; acc[3] += v.w * nn;
            } else {
                float2 v = *(const float2*)hp;
                acc[0] += v.x * nn; acc[1] += v.y * nn;
            }
        }
    }

    float inv = g_invdeg[w];
    const float* hp = h + (size_t)w * D + lane * V;
    const float* bp = bias + lane * V;
    float* op = zo + (size_t)w * D + lane * V;
    if (V == 4) {
        float4 sv = *(const float4*)hp;
        float4 bv = *(const float4*)bp;
        float4 o;
        o.x = acc[0] + sv.x * inv + bv.x;
        o.y = acc[1] + sv.y * inv + bv.y;
        o.z = acc[2] + sv.z * inv + bv.z;
        o.w = acc[3] + sv.w * inv + bv.w;
        if (RELU) { o.x = fmaxf(o.x, 0.f); o.y = fmaxf(o.y, 0.f);
                    o.z = fmaxf(o.z, 0.f); o.w = fmaxf(o.w, 0.f); }
        *(float4*)op = o;
    } else {
        float2 sv = *(const float2*)hp;
        float2 bv = *(const float2*)bp;
        float2 o;
        o.x = acc[0] + sv.x * inv + bv.x;
        o.y = acc[1] + sv.y * inv + bv.y;
        if (RELU) { o.x = fmaxf(o.x, 0.f); o.y = fmaxf(o.y, 0.f); }
        *(float2*)op = o;
    }
}

// ---------------- decode: dot over 64 dims, 16 lanes per edge --------------
__global__ void k_decode(const int* __restrict__ li, float* __restrict__ out) {
    int gid = blockIdx.x * blockDim.x + threadIdx.x;
    int e = gid >> 4;
    int l = gid & 15;
    if (e >= NL) return;
    int a = li[e];
    int b = li[NL + e];
    float4 va = *(const float4*)(g_z2 + (size_t)a * DOUT + l * 4);
    float4 vb = *(const float4*)(g_z2 + (size_t)b * DOUT + l * 4);
    float d = va.x * vb.x + va.y * vb.y + va.z * vb.z + va.w * vb.w;
    d += __shfl_xor_sync(0xffffffffu, d, 1);
    d += __shfl_xor_sync(0xffffffffu, d, 2);
    d += __shfl_xor_sync(0xffffffffu, d, 4);
    d += __shfl_xor_sync(0xffffffffu, d, 8);
    if (l == 0) out[e] = d;
}

// ---------------- launch ----------------------------------------------------
extern "C" void kernel_launch(void* const* d_in, const int* in_sizes, int n_in,
                              void* d_out, int out_size) {
    const float* x   = (const float*)d_in[0];
    const int*   ei  = (const int*)d_in[1];
    const int*   eli = (const int*)d_in[2];
    const float* W1  = (const float*)d_in[3];
    const float* b1  = (const float*)d_in[4];
    const float* W2  = (const float*)d_in[5];
    const float* b2  = (const float*)d_in[6];
    float* out = (float*)d_out;

    float *p_h1, *p_z, *p_h2, *p_z2;
    cudaGetSymbolAddress((void**)&p_h1, g_h1);
    cudaGetSymbolAddress((void**)&p_z,  g_z);
    cudaGetSymbolAddress((void**)&p_h2, g_h2);
    cudaGetSymbolAddress((void**)&p_z2, g_z2);

    const int NB_NODE = (NN + 255) / 256;        // 391
    const int NB_EDGE = (NE + 255) / 256;        // 6250
    const int NB_SCAN = (NN + 1023) / 1024;      // 98
    const int NB_GEMM = (NN + 127) / 128;        // 782
    const int NB_AGG  = (NN * 32 + 255) / 256;   // 12500
    const int NB_DEC  = (NL * 16 + 255) / 256;   // 12500

    k_zero_deg<<<NB_NODE, 256>>>();
    k_degree<<<NB_EDGE, 256>>>(ei);
    k_dinv<<<NB_NODE, 256>>>();
    k_scan1<<<NB_SCAN, 1024>>>(NN);
    k_scan2<<<1, 128>>>(NB_SCAN);
    k_scan3<<<NB_SCAN, 1024>>>(NN);
    k_scatter<<<NB_EDGE, 256>>>(ei);

    k_gemm<DH><<<NB_GEMM, 256>>>(x, W1, p_h1, NN);         // h1 = x @ W1
    k_agg<DH, true><<<NB_AGG, 256>>>(p_h1, b1, p_z);       // z = relu(A_norm h1 + b1)
    k_gemm<DOUT><<<NB_GEMM, 256>>>(p_z, W2, p_h2, NN);     // h2 = z @ W2
    k_agg<DOUT, false><<<NB_AGG, 256>>>(p_h2, b2, p_z2);   // z2 = A_norm h2 + b2
    k_decode<<<NB_DEC, 256>>>(eli, out);
}

// round 3
// speedup vs baseline: 1.3173x; 1.3173x over previous
#include <cuda_runtime.h>
#include <cuda_bf16.h>
#include <cstdint>

#define NN 100000
#define NE 1600000
#define NL 200000
#define DH  128
#define DOUT 64

// ====================== scratch (device globals) =============================
__device__ __align__(16) int   g_deg[NN];
__device__ __align__(16) float g_dinv[NN];
__device__ __align__(16) float g_invdeg[NN];
__device__ __align__(16) int   g_off[NN + 1];
__device__ __align__(16) int   g_cursor[NN];
__device__ __align__(16) int   g_csr[NE];
__device__ __align__(16) int   g_bsum[128];
__device__ __align__(16) float g_h1[(size_t)NN * DH];
__device__ __align__(16) float g_z [(size_t)NN * DH];
__device__ __align__(16) float g_h2[(size_t)NN * DOUT];
__device__ __align__(16) float g_z2[(size_t)NN * DOUT];
// prepped W^T in bf16 hi/lo: [N][128] row-major (K contiguous)
__device__ __align__(16) __nv_bfloat16 g_w1h[128 * 128];
__device__ __align__(16) __nv_bfloat16 g_w1l[128 * 128];
__device__ __align__(16) __nv_bfloat16 g_w2h[64 * 128];
__device__ __align__(16) __nv_bfloat16 g_w2l[64 * 128];

// ====================== small helpers ========================================
__device__ __forceinline__ uint32_t smem_u32(const void* p) {
    uint32_t a;
    asm("{ .reg .u64 t; cvta.to.shared.u64 t, %1; cvt.u32.u64 %0, t; }" : "=r"(a) : "l"(p));
    return a;
}
__device__ __forceinline__ void ldmx4(uint32_t* r, uint32_t addr) {
    asm volatile("ldmatrix.sync.aligned.m8n8.x4.shared.b16 {%0,%1,%2,%3}, [%4];"
                 : "=r"(r[0]), "=r"(r[1]), "=r"(r[2]), "=r"(r[3]) : "r"(addr));
}
__device__ __forceinline__ void ldmx2(uint32_t* r, uint32_t addr) {
    asm volatile("ldmatrix.sync.aligned.m8n8.x2.shared.b16 {%0,%1}, [%2];"
                 : "=r"(r[0]), "=r"(r[1]) : "r"(addr));
}
__device__ __forceinline__ void mma16816(float* c, const uint32_t* a, const uint32_t* b) {
    asm volatile(
        "mma.sync.aligned.m16n8k16.row.col.f32.bf16.bf16.f32 "
        "{%0,%1,%2,%3}, {%4,%5,%6,%7}, {%8,%9}, {%0,%1,%2,%3};"
        : "+f"(c[0]), "+f"(c[1]), "+f"(c[2]), "+f"(c[3])
        : "r"(a[0]), "r"(a[1]), "r"(a[2]), "r"(a[3]), "r"(b[0]), "r"(b[1]));
}

// ====================== setup kernels ========================================
__global__ void k_zero_deg() {
    int i = blockIdx.x * blockDim.x + threadIdx.x;
    if (i < NN) g_deg[i] = 0;
}
__global__ void k_degree(const int* __restrict__ ei) {
    int e = blockIdx.x * blockDim.x + threadIdx.x;
    if (e < NE) atomicAdd(&g_deg[ei[NE + e]], 1);
}
__global__ void k_dinv() {
    int i = blockIdx.x * blockDim.x + threadIdx.x;
    if (i < NN) {
        float d = (float)(g_deg[i] + 1);
        g_dinv[i]   = rsqrtf(d);
        g_invdeg[i] = 1.0f / d;
    }
}
__global__ void k_scan1(int n) {
    __shared__ int wsum[32];
    int t = threadIdx.x;
    int gid = blockIdx.x * 1024 + t;
    int v = (gid < n) ? g_deg[gid] : 0;
    int x = v;
    #pragma unroll
    for (int o = 1; o < 32; o <<= 1) {
        int y = __shfl_up_sync(0xffffffffu, x, o);
        if ((t & 31) >= o) x += y;
    }
    if ((t & 31) == 31) wsum[t >> 5] = x;
    __syncthreads();
    if (t < 32) {
        int w = wsum[t];
        int xx = w;
        #pragma unroll
        for (int o = 1; o < 32; o <<= 1) {
            int y = __shfl_up_sync(0xffffffffu, xx, o);
            if (t >= o) xx += y;
        }
        wsum[t] = xx - w;
    }
    __syncthreads();
    int excl = x - v + wsum[t >> 5];
    if (gid < n) g_off[gid] = excl;
    if (t == 1023) g_bsum[blockIdx.x] = excl + v;
}
__global__ void k_scan2(int nb) {
    __shared__ int s[128];
    int t = threadIdx.x;
    int v = (t < nb) ? g_bsum[t] : 0;
    s[t] = v;
    __syncthreads();
    for (int o = 1; o < 128; o <<= 1) {
        int x = (t >= o) ? s[t - o] : 0;
        __syncthreads();
        s[t] += x;
        __syncthreads();
    }
    if (t < nb) g_bsum[t] = s[t] - v;
}
__global__ void k_scan3(int n) {
    int t = threadIdx.x;
    int gid = blockIdx.x * 1024 + t;
    if (gid < n) {
        int v = g_off[gid] + g_bsum[blockIdx.x];
        g_off[gid]    = v;
        g_cursor[gid] = v;
    }
    if (gid == 0) g_off[n] = NE;
}
__global__ void k_scatter(const int* __restrict__ ei) {
    int e = blockIdx.x * blockDim.x + threadIdx.x;
    if (e < NE) {
        int s = ei[e];
        int d = ei[NE + e];
        int p = atomicAdd(&g_cursor[d], 1);
        g_csr[p] = s;
    }
}

// ====================== W prep: transpose + bf16 hi/lo =======================
template <int N>
__global__ void k_prepw(const float* __restrict__ W,
                        __nv_bfloat16* __restrict__ wh,
                        __nv_bfloat16* __restrict__ wl) {
    int idx = blockIdx.x * blockDim.x + threadIdx.x;
    if (idx >= N * 128) return;
    int n = idx >> 7;
    int k = idx & 127;
    float v = W[k * N + n];
    __nv_bfloat16 h = __float2bfloat16_rn(v);
    __nv_bfloat16 l = __float2bfloat16_rn(v - __bfloat162float(h));
    wh[n * 128 + k] = h;
    wl[n * 128 + k] = l;
}

// ====================== HMMA GEMM: C[M,N] = A[M,128] @ W[128,N] ==============
// 3-term bf16 split: Ah*Bh + Ah*Bl + Al*Bh, fp32 accumulation.
// CTA tile: 128 x N, K=128 in one shot. 8 warps: 4(m) x 2(n), warp = 32 x N/2.
template <int N>
__global__ void __launch_bounds__(256, 1) k_gemm_mma(
    const float* __restrict__ A,
    const __nv_bfloat16* __restrict__ Bh,
    const __nv_bfloat16* __restrict__ Bl,
    float* __restrict__ C, int M) {
    const int SP = 136;             // padded row stride (bf16 elems)
    const int WN = N / 2;           // warp n-width: 64 (N=128) or 32 (N=64)
    const int NS = WN / 8;          // n-subtiles per warp
    extern __shared__ __align__(16) __nv_bfloat16 sm[];
    __nv_bfloat16* As_h = sm;                    // [128][SP]
    __nv_bfloat16* As_l = sm + 128 * SP;
    __nv_bfloat16* Bs_h = sm + 2 * 128 * SP;     // [N][SP]
    __nv_bfloat16* Bs_l = sm + 2 * 128 * SP + N * SP;

    int tid = threadIdx.x, lane = tid & 31, wid = tid >> 5;
    int row0 = blockIdx.x * 128;

    // --- fill A (convert fp32 -> bf16 hi/lo) ---
    #pragma unroll
    for (int i = tid; i < 4096; i += 256) {      // 4096 float4 quads
        int r  = i >> 5;
        int c4 = (i & 31) << 2;
        int row = row0 + r;
        float4 v = (row < M) ? *(const float4*)(A + (size_t)row * 128 + c4)
                             : make_float4(0.f, 0.f, 0.f, 0.f);
        __nv_bfloat16 h0 = __float2bfloat16_rn(v.x);
        __nv_bfloat16 h1 = __float2bfloat16_rn(v.y);
        __nv_bfloat16 h2 = __float2bfloat16_rn(v.z);
        __nv_bfloat16 h3 = __float2bfloat16_rn(v.w);
        __nv_bfloat16 l0 = __float2bfloat16_rn(v.x - __bfloat162float(h0));
        __nv_bfloat16 l1 = __float2bfloat16_rn(v.y - __bfloat162float(h1));
        __nv_bfloat16 l2 = __float2bfloat16_rn(v.z - __bfloat162float(h2));
        __nv_bfloat16 l3 = __float2bfloat16_rn(v.w - __bfloat162float(h3));
        __nv_bfloat162 hp0 = __halves2bfloat162(h0, h1);
        __nv_bfloat162 hp1 = __halves2bfloat162(h2, h3);
        __nv_bfloat162 lp0 = __halves2bfloat162(l0, l1);
        __nv_bfloat162 lp1 = __halves2bfloat162(l2, l3);
        int o = r * SP + c4;
        *(uint2*)(As_h + o) = make_uint2(*(uint32_t*)&hp0, *(uint32_t*)&hp1);
        *(uint2*)(As_l + o) = make_uint2(*(uint32_t*)&lp0, *(uint32_t*)&lp1);
    }
    // --- fill B (copy prepped bf16) ---
    #pragma unroll
    for (int i = tid; i < N * 16; i += 256) {    // N*128 bf16 / 8 per uint4
        int r  = i >> 4;
        int c8 = (i & 15) << 3;
        uint4 vh = *(const uint4*)(Bh + r * 128 + c8);
        uint4 vl = *(const uint4*)(Bl + r * 128 + c8);
        *(uint4*)(Bs_h + r * SP + c8) = vh;
        *(uint4*)(Bs_l + r * SP + c8) = vl;
    }
    __syncthreads();

    int wm = (wid >> 1) * 32;       // warp m origin
    int wn = (wid & 1) * WN;        // warp n origin

    float acc[2][NS][4];
    #pragma unroll
    for (int ms = 0; ms < 2; ms++)
        #pragma unroll
        for (int ns = 0; ns < NS; ns++)
            #pragma unroll
            for (int q = 0; q < 4; q++) acc[ms][ns][q] = 0.f;

    uint32_t base_ah = smem_u32(As_h);
    uint32_t base_al = smem_u32(As_l);
    uint32_t base_bh = smem_u32(Bs_h);
    uint32_t base_bl = smem_u32(Bs_l);

    #pragma unroll
    for (int k0 = 0; k0 < 128; k0 += 16) {
        uint32_t a_h[2][4], a_l[2][4];
        #pragma unroll
        for (int ms = 0; ms < 2; ms++) {
            int ar = wm + ms * 16 + (lane & 15);
            int ac = k0 + (lane >> 4) * 8;
            uint32_t off = (uint32_t)(ar * SP + ac) * 2;
            ldmx4(a_h[ms], base_ah + off);
            ldmx4(a_l[ms], base_al + off);
        }
        uint32_t b_h[NS][2], b_l[NS][2];
        #pragma unroll
        for (int ns = 0; ns < NS; ns++) {
            int br = wn + ns * 8 + (lane & 7);
            int bc = k0 + (((lane & 15) >> 3)) * 8;
            uint32_t off = (uint32_t)(br * SP + bc) * 2;
            ldmx2(b_h[ns], base_bh + off);
            ldmx2(b_l[ns], base_bl + off);
        }
        #pragma unroll
        for (int ms = 0; ms < 2; ms++)
            #pragma unroll
            for (int ns = 0; ns < NS; ns++) {
                mma16816(acc[ms][ns], a_h[ms], b_h[ns]);
                mma16816(acc[ms][ns], a_h[ms], b_l[ns]);
                mma16816(acc[ms][ns], a_l[ms], b_h[ns]);
            }
    }

    // --- epilogue ---
    int gID = lane >> 2, tig = lane & 3;
    #pragma unroll
    for (int ms = 0; ms < 2; ms++) {
        int r0 = row0 + wm + ms * 16 + gID;
        #pragma unroll
        for (int ns = 0; ns < NS; ns++) {
            int col = wn + ns * 8 + tig * 2;
            if (r0 < M)
                *(float2*)(C + (size_t)r0 * N + col) = make_float2(acc[ms][ns][0], acc[ms][ns][1]);
            if (r0 + 8 < M)
                *(float2*)(C + (size_t)(r0 + 8) * N + col) = make_float2(acc[ms][ns][2], acc[ms][ns][3]);
        }
    }
}

// ====================== aggregation: one warp per node =======================
template <int D, bool RELU>
__global__ void k_agg(const float* __restrict__ h, const float* __restrict__ bias,
                      float* __restrict__ zo) {
    int w    = (blockIdx.x * blockDim.x + threadIdx.x) >> 5;
    int lane = threadIdx.x & 31;
    if (w >= NN) return;
    const int V = D / 32;
    int beg = g_off[w], end = g_off[w + 1];
    float di = g_dinv[w];
    float acc[V];
    #pragma unroll
    for (int i = 0; i < V; i++) acc[i] = 0.0f;

    for (int base = beg; base < end; base += 32) {
        int e = base + lane;
        int s = 0; float nm = 0.0f;
        if (e < end) { s = g_csr[e]; nm = g_dinv[s] * di; }
        int cnt = min(32, end - base);
        for (int j = 0; j < cnt; j++) {
            int ss   = __shfl_sync(0xffffffffu, s, j);
            float nn = __shfl_sync(0xffffffffu, nm, j);
            const float* hp = h + (size_t)ss * D + lane * V;
            if (V == 4) {
                float4 v = *(const float4*)hp;
                acc[0] += v.x * nn; acc[1] += v.y * nn;
                acc[2] += v.z * nn; acc[3] += v.w * nn;
            } else {
                float2 v = *(const float2*)hp;
                acc[0] += v.x * nn; acc[1] += v.y * nn;
            }
        }
    }

    float inv = g_invdeg[w];
    const float* hp = h + (size_t)w * D + lane * V;
    const float* bp = bias + lane * V;
    float* op = zo + (size_t)w * D + lane * V;
    if (V == 4) {
        float4 sv = *(const float4*)hp;
        float4 bv = *(const float4*)bp;
        float4 o;
        o.x = acc[0] + sv.x * inv + bv.x;
        o.y = acc[1] + sv.y * inv + bv.y;
        o.z = acc[2] + sv.z * inv + bv.z;
        o.w = acc[3] + sv.w * inv + bv.w;
        if (RELU) { o.x = fmaxf(o.x, 0.f); o.y = fmaxf(o.y, 0.f);
                    o.z = fmaxf(o.z, 0.f); o.w = fmaxf(o.w, 0.f); }
        *(float4*)op = o;
    } else {
        float2 sv = *(const float2*)hp;
        float2 bv = *(const float2*)bp;
        float2 o;
        o.x = acc[0] + sv.x * inv + bv.x;
        o.y = acc[1] + sv.y * inv + bv.y;
        if (RELU) { o.x = fmaxf(o.x, 0.f); o.y = fmaxf(o.y, 0.f); }
        *(float2*)op = o;
    }
}

// ====================== decode ===============================================
__global__ void k_decode(const int* __restrict__ li, float* __restrict__ out) {
    int gid = blockIdx.x * blockDim.x + threadIdx.x;
    int e = gid >> 4;
    int l = gid & 15;
    if (e >= NL) return;
    int a = li[e];
    int b = li[NL + e];
    float4 va = *(const float4*)(g_z2 + (size_t)a * DOUT + l * 4);
    float4 vb = *(const float4*)(g_z2 + (size_t)b * DOUT + l * 4);
    float d = va.x * vb.x + va.y * vb.y + va.z * vb.z + va.w * vb.w;
    d += __shfl_xor_sync(0xffffffffu, d, 1);
    d += __shfl_xor_sync(0xffffffffu, d, 2);
    d += __shfl_xor_sync(0xffffffffu, d, 4);
    d += __shfl_xor_sync(0xffffffffu, d, 8);
    if (l == 0) out[e] = d;
}

// ====================== launch ===============================================
extern "C" void kernel_launch(void* const* d_in, const int* in_sizes, int n_in,
                              void* d_out, int out_size) {
    const float* x   = (const float*)d_in[0];
    const int*   ei  = (const int*)d_in[1];
    const int*   eli = (const int*)d_in[2];
    const float* W1  = (const float*)d_in[3];
    const float* b1  = (const float*)d_in[4];
    const float* W2  = (const float*)d_in[5];
    const float* b2  = (const float*)d_in[6];
    float* out = (float*)d_out;

    float *p_h1, *p_z, *p_h2, *p_z2;
    __nv_bfloat16 *p_w1h, *p_w1l, *p_w2h, *p_w2l;
    cudaGetSymbolAddress((void**)&p_h1, g_h1);
    cudaGetSymbolAddress((void**)&p_z,  g_z);
    cudaGetSymbolAddress((void**)&p_h2, g_h2);
    cudaGetSymbolAddress((void**)&p_z2, g_z2);
    cudaGetSymbolAddress((void**)&p_w1h, g_w1h);
    cudaGetSymbolAddress((void**)&p_w1l, g_w1l);
    cudaGetSymbolAddress((void**)&p_w2h, g_w2h);
    cudaGetSymbolAddress((void**)&p_w2l, g_w2l);

    const int SP = 136;
    const int SMEM1 = (2 * 128 * SP + 2 * 128 * SP) * 2;  // 139264 B
    const int SMEM2 = (2 * 128 * SP + 2 * 64 * SP) * 2;   // 104448 B
    cudaFuncSetAttribute(k_gemm_mma<128>, cudaFuncAttributeMaxDynamicSharedMemorySize, SMEM1);
    cudaFuncSetAttribute(k_gemm_mma<64>,  cudaFuncAttributeMaxDynamicSharedMemorySize, SMEM2);

    const int NB_NODE = (NN + 255) / 256;
    const int NB_EDGE = (NE + 255) / 256;
    const int NB_SCAN = (NN + 1023) / 1024;
    const int NB_GEMM = (NN + 127) / 128;
    const int NB_AGG  = (NN * 32 + 255) / 256;
    const int NB_DEC  = (NL * 16 + 255) / 256;

    k_zero_deg<<<NB_NODE, 256>>>();
    k_degree<<<NB_EDGE, 256>>>(ei);
    k_dinv<<<NB_NODE, 256>>>();
    k_scan1<<<NB_SCAN, 1024>>>(NN);
    k_scan2<<<1, 128>>>(NB_SCAN);
    k_scan3<<<NB_SCAN, 1024>>>(NN);
    k_scatter<<<NB_EDGE, 256>>>(ei);

    k_prepw<128><<<(128 * 128 + 255) / 256, 256>>>(W1, p_w1h, p_w1l);
    k_prepw<64><<<(64 * 128 + 255) / 256, 256>>>(W2, p_w2h, p_w2l);

    k_gemm_mma<128><<<NB_GEMM, 256, SMEM1>>>(x, p_w1h, p_w1l, p_h1, NN);   // h1 = x @ W1
    k_agg<DH, true><<<NB_AGG, 256>>>(p_h1, b1, p_z);                       // z = relu(Ah1+b1)
    k_gemm_mma<64><<<NB_GEMM, 256, SMEM2>>>(p_z, p_w2h, p_w2l, p_h2, NN);  // h2 = z @ W2
    k_agg<DOUT, false><<<NB_AGG, 256>>>(p_h2, b2, p_z2);                   // z2 = Ah2+b2
    k_decode<<<NB_DEC, 256>>>(eli, out);
}

// round 4
// speedup vs baseline: 1.4010x; 1.0636x over previous
#include <cuda_runtime.h>
#include <cuda_bf16.h>
#include <cstdint>

#define NN 100000
#define NE 1600000
#define NL 200000
#define DH  128
#define DOUT 64

// ====================== scratch (device globals) =============================
__device__ __align__(16) int   g_deg[NN];
__device__ __align__(16) float g_dinv[NN];
__device__ __align__(16) float g_invdeg[NN];
__device__ __align__(16) int   g_off[NN + 1];
__device__ __align__(16) int   g_cursor[NN];
__device__ __align__(16) int   g_csr[NE];
__device__ __align__(16) int   g_bsum[128];
__device__ __align__(16) float g_h1[(size_t)NN * DH];
__device__ __align__(16) float g_z [(size_t)NN * DH];
__device__ __align__(16) float g_h2[(size_t)NN * DOUT];
__device__ __align__(16) float g_z2[(size_t)NN * DOUT];
// prepped W^T in bf16 hi/lo: [N][128] row-major (K contiguous)
__device__ __align__(16) __nv_bfloat16 g_w1h[128 * 128];
__device__ __align__(16) __nv_bfloat16 g_w1l[128 * 128];
__device__ __align__(16) __nv_bfloat16 g_w2h[64 * 128];
__device__ __align__(16) __nv_bfloat16 g_w2l[64 * 128];

// ====================== small helpers ========================================
__device__ __forceinline__ uint32_t smem_u32(const void* p) {
    uint32_t a;
    asm("{ .reg .u64 t; cvta.to.shared.u64 t, %1; cvt.u32.u64 %0, t; }" : "=r"(a) : "l"(p));
    return a;
}
__device__ __forceinline__ void ldmx4(uint32_t* r, uint32_t addr) {
    asm volatile("ldmatrix.sync.aligned.m8n8.x4.shared.b16 {%0,%1,%2,%3}, [%4];"
                 : "=r"(r[0]), "=r"(r[1]), "=r"(r[2]), "=r"(r[3]) : "r"(addr));
}
__device__ __forceinline__ void ldmx2(uint32_t* r, uint32_t addr) {
    asm volatile("ldmatrix.sync.aligned.m8n8.x2.shared.b16 {%0,%1}, [%2];"
                 : "=r"(r[0]), "=r"(r[1]) : "r"(addr));
}
__device__ __forceinline__ void mma16816(float* c, const uint32_t* a, const uint32_t* b) {
    asm volatile(
        "mma.sync.aligned.m16n8k16.row.col.f32.bf16.bf16.f32 "
        "{%0,%1,%2,%3}, {%4,%5,%6,%7}, {%8,%9}, {%0,%1,%2,%3};"
        : "+f"(c[0]), "+f"(c[1]), "+f"(c[2]), "+f"(c[3])
        : "r"(a[0]), "r"(a[1]), "r"(a[2]), "r"(a[3]), "r"(b[0]), "r"(b[1]));
}

// ====================== setup kernels ========================================
__global__ void k_zero_deg() {
    int i = blockIdx.x * blockDim.x + threadIdx.x;
    if (i < NN) g_deg[i] = 0;
}
__global__ void k_degree(const int* __restrict__ ei) {
    int e = blockIdx.x * blockDim.x + threadIdx.x;
    if (e < NE) atomicAdd(&g_deg[ei[NE + e]], 1);
}
// scan phase 1 + dinv/invdeg fused (loads g_deg anyway)
__global__ void k_scan1(int n) {
    __shared__ int wsum[32];
    int t = threadIdx.x;
    int gid = blockIdx.x * 1024 + t;
    int v = (gid < n) ? g_deg[gid] : 0;
    if (gid < n) {
        float d = (float)(v + 1);
        g_dinv[gid]   = rsqrtf(d);
        g_invdeg[gid] = 1.0f / d;
    }
    int x = v;
    #pragma unroll
    for (int o = 1; o < 32; o <<= 1) {
        int y = __shfl_up_sync(0xffffffffu, x, o);
        if ((t & 31) >= o) x += y;
    }
    if ((t & 31) == 31) wsum[t >> 5] = x;
    __syncthreads();
    if (t < 32) {
        int w = wsum[t];
        int xx = w;
        #pragma unroll
        for (int o = 1; o < 32; o <<= 1) {
            int y = __shfl_up_sync(0xffffffffu, xx, o);
            if (t >= o) xx += y;
        }
        wsum[t] = xx - w;
    }
    __syncthreads();
    int excl = x - v + wsum[t >> 5];
    if (gid < n) g_off[gid] = excl;
    if (t == 1023) g_bsum[blockIdx.x] = excl + v;
}
__global__ void k_scan2(int nb) {
    __shared__ int s[128];
    int t = threadIdx.x;
    int v = (t < nb) ? g_bsum[t] : 0;
    s[t] = v;
    __syncthreads();
    for (int o = 1; o < 128; o <<= 1) {
        int x = (t >= o) ? s[t - o] : 0;
        __syncthreads();
        s[t] += x;
        __syncthreads();
    }
    if (t < nb) g_bsum[t] = s[t] - v;
}
__global__ void k_scan3(int n) {
    int t = threadIdx.x;
    int gid = blockIdx.x * 1024 + t;
    if (gid < n) {
        int v = g_off[gid] + g_bsum[blockIdx.x];
        g_off[gid]    = v;
        g_cursor[gid] = v;
    }
    if (gid == 0) g_off[n] = NE;
}
__global__ void k_scatter(const int* __restrict__ ei) {
    int e = blockIdx.x * blockDim.x + threadIdx.x;
    if (e < NE) {
        int s = ei[e];
        int d = ei[NE + e];
        int p = atomicAdd(&g_cursor[d], 1);
        g_csr[p] = s;
    }
}

// ====================== W prep: transpose + bf16 hi/lo =======================
template <int N>
__global__ void k_prepw(const float* __restrict__ W,
                        __nv_bfloat16* __restrict__ wh,
                        __nv_bfloat16* __restrict__ wl) {
    int idx = blockIdx.x * blockDim.x + threadIdx.x;
    if (idx >= N * 128) return;
    int n = idx >> 7;
    int k = idx & 127;
    float v = W[k * N + n];
    __nv_bfloat16 h = __float2bfloat16_rn(v);
    __nv_bfloat16 l = __float2bfloat16_rn(v - __bfloat162float(h));
    wh[n * 128 + k] = h;
    wl[n * 128 + k] = l;
}

// ====================== HMMA GEMM: C[M,N] = A[M,128] @ W[128,N] ==============
// 3-term bf16 split: Ah*Bh + Ah*Bl + Al*Bh, fp32 accumulation.
// CTA tile: 128 x N, K=128 in one shot. 8 warps: 4(m) x 2(n), warp = 32 x N/2.
template <int N>
__global__ void __launch_bounds__(256, 1) k_gemm_mma(
    const float* __restrict__ A,
    const __nv_bfloat16* __restrict__ Bh,
    const __nv_bfloat16* __restrict__ Bl,
    float* __restrict__ C, int M) {
    const int SP = 136;             // padded row stride (bf16 elems)
    const int WN = N / 2;           // warp n-width: 64 (N=128) or 32 (N=64)
    const int NS = WN / 8;          // n-subtiles per warp
    extern __shared__ __align__(16) __nv_bfloat16 sm[];
    __nv_bfloat16* As_h = sm;                    // [128][SP]
    __nv_bfloat16* As_l = sm + 128 * SP;
    __nv_bfloat16* Bs_h = sm + 2 * 128 * SP;     // [N][SP]
    __nv_bfloat16* Bs_l = sm + 2 * 128 * SP + N * SP;

    int tid = threadIdx.x, lane = tid & 31, wid = tid >> 5;
    int row0 = blockIdx.x * 128;

    // --- fill B first (pure copy; loads overlap A-convert ALU work) ---
    #pragma unroll
    for (int i = tid; i < N * 16; i += 256) {    // N*128 bf16 / 8 per uint4
        int r  = i >> 4;
        int c8 = (i & 15) << 3;
        uint4 vh = *(const uint4*)(Bh + r * 128 + c8);
        uint4 vl = *(const uint4*)(Bl + r * 128 + c8);
        *(uint4*)(Bs_h + r * SP + c8) = vh;
        *(uint4*)(Bs_l + r * SP + c8) = vl;
    }
    // --- fill A (convert fp32 -> bf16 hi/lo) ---
    #pragma unroll
    for (int i = tid; i < 4096; i += 256) {      // 4096 float4 quads
        int r  = i >> 5;
        int c4 = (i & 31) << 2;
        int row = row0 + r;
        float4 v = (row < M) ? *(const float4*)(A + (size_t)row * 128 + c4)
                             : make_float4(0.f, 0.f, 0.f, 0.f);
        __nv_bfloat16 h0 = __float2bfloat16_rn(v.x);
        __nv_bfloat16 h1 = __float2bfloat16_rn(v.y);
        __nv_bfloat16 h2 = __float2bfloat16_rn(v.z);
        __nv_bfloat16 h3 = __float2bfloat16_rn(v.w);
        __nv_bfloat16 l0 = __float2bfloat16_rn(v.x - __bfloat162float(h0));
        __nv_bfloat16 l1 = __float2bfloat16_rn(v.y - __bfloat162float(h1));
        __nv_bfloat16 l2 = __float2bfloat16_rn(v.z - __bfloat162float(h2));
        __nv_bfloat16 l3 = __float2bfloat16_rn(v.w - __bfloat162float(h3));
        __nv_bfloat162 hp0 = __halves2bfloat162(h0, h1);
        __nv_bfloat162 hp1 = __halves2bfloat162(h2, h3);
        __nv_bfloat162 lp0 = __halves2bfloat162(l0, l1);
        __nv_bfloat162 lp1 = __halves2bfloat162(l2, l3);
        int o = r * SP + c4;
        *(uint2*)(As_h + o) = make_uint2(*(uint32_t*)&hp0, *(uint32_t*)&hp1);
        *(uint2*)(As_l + o) = make_uint2(*(uint32_t*)&lp0, *(uint32_t*)&lp1);
    }
    __syncthreads();

    int wm = (wid >> 1) * 32;       // warp m origin
    int wn = (wid & 1) * WN;        // warp n origin

    float acc[2][NS][4];
    #pragma unroll
    for (int ms = 0; ms < 2; ms++)
        #pragma unroll
        for (int ns = 0; ns < NS; ns++)
            #pragma unroll
            for (int q = 0; q < 4; q++) acc[ms][ns][q] = 0.f;

    uint32_t base_ah = smem_u32(As_h);
    uint32_t base_al = smem_u32(As_l);
    uint32_t base_bh = smem_u32(Bs_h);
    uint32_t base_bl = smem_u32(Bs_l);

    #pragma unroll
    for (int k0 = 0; k0 < 128; k0 += 16) {
        uint32_t a_h[2][4], a_l[2][4];
        #pragma unroll
        for (int ms = 0; ms < 2; ms++) {
            int ar = wm + ms * 16 + (lane & 15);
            int ac = k0 + (lane >> 4) * 8;
            uint32_t off = (uint32_t)(ar * SP + ac) * 2;
            ldmx4(a_h[ms], base_ah + off);
            ldmx4(a_l[ms], base_al + off);
        }
        uint32_t b_h[NS][2], b_l[NS][2];
        #pragma unroll
        for (int ns = 0; ns < NS; ns++) {
            int br = wn + ns * 8 + (lane & 7);
            int bc = k0 + (((lane & 15) >> 3)) * 8;
            uint32_t off = (uint32_t)(br * SP + bc) * 2;
            ldmx2(b_h[ns], base_bh + off);
            ldmx2(b_l[ns], base_bl + off);
        }
        #pragma unroll
        for (int ms = 0; ms < 2; ms++)
            #pragma unroll
            for (int ns = 0; ns < NS; ns++) {
                mma16816(acc[ms][ns], a_h[ms], b_h[ns]);
                mma16816(acc[ms][ns], a_h[ms], b_l[ns]);
                mma16816(acc[ms][ns], a_l[ms], b_h[ns]);
            }
    }

    // --- epilogue ---
    int gID = lane >> 2, tig = lane & 3;
    #pragma unroll
    for (int ms = 0; ms < 2; ms++) {
        int r0 = row0 + wm + ms * 16 + gID;
        #pragma unroll
        for (int ns = 0; ns < NS; ns++) {
            int col = wn + ns * 8 + tig * 2;
            if (r0 < M)
                *(float2*)(C + (size_t)r0 * N + col) = make_float2(acc[ms][ns][0], acc[ms][ns][1]);
            if (r0 + 8 < M)
                *(float2*)(C + (size_t)(r0 + 8) * N + col) = make_float2(acc[ms][ns][2], acc[ms][ns][3]);
        }
    }
}

// ====================== aggregation: one warp per node =======================
template <int D, bool RELU>
__global__ void k_agg(const float* __restrict__ h, const float* __restrict__ bias,
                      float* __restrict__ zo) {
    int w    = (blockIdx.x * blockDim.x + threadIdx.x) >> 5;
    int lane = threadIdx.x & 31;
    if (w >= NN) return;
    const int V = D / 32;
    int beg = g_off[w], end = g_off[w + 1];
    float di = g_dinv[w];
    float acc[V];
    #pragma unroll
    for (int i = 0; i < V; i++) acc[i] = 0.0f;

    for (int base = beg; base < end; base += 32) {
        int e = base + lane;
        int s = 0; float nm = 0.0f;
        if (e < end) { s = g_csr[e]; nm = g_dinv[s] * di; }
        int cnt = min(32, end - base);
        int j = 0;
        // 2-wide unroll: two independent gathers in flight
        for (; j + 1 < cnt; j += 2) {
            int   s0 = __shfl_sync(0xffffffffu, s,  j);
            float n0 = __shfl_sync(0xffffffffu, nm, j);
            int   s1 = __shfl_sync(0xffffffffu, s,  j + 1);
            float n1 = __shfl_sync(0xffffffffu, nm, j + 1);
            const float* p0 = h + (size_t)s0 * D + lane * V;
            const float* p1 = h + (size_t)s1 * D + lane * V;
            if (V == 4) {
                float4 v0 = *(const float4*)p0;
                float4 v1 = *(const float4*)p1;
                acc[0] += v0.x * n0; acc[1] += v0.y * n0;
                acc[2] += v0.z * n0; acc[3] += v0.w * n0;
                acc[0] += v1.x * n1; acc[1] += v1.y * n1;
                acc[2] += v1.z * n1; acc[3] += v1.w * n1;
            } else {
                float2 v0 = *(const float2*)p0;
                float2 v1 = *(const float2*)p1;
                acc[0] += v0.x * n0; acc[1] += v0.y * n0;
                acc[0] += v1.x * n1; acc[1] += v1.y * n1;
            }
        }
        if (j < cnt) {
            int   s0 = __shfl_sync(0xffffffffu, s,  j);
            float n0 = __shfl_sync(0xffffffffu, nm, j);
            const float* p0 = h + (size_t)s0 * D + lane * V;
            if (V == 4) {
                float4 v0 = *(const float4*)p0;
                acc[0] += v0.x * n0; acc[1] += v0.y * n0;
                acc[2] += v0.z * n0; acc[3] += v0.w * n0;
            } else {
                float2 v0 = *(const float2*)p0;
                acc[0] += v0.x * n0; acc[1] += v0.y * n0;
            }
        }
    }

    float inv = g_invdeg[w];
    const float* hp = h + (size_t)w * D + lane * V;
    const float* bp = bias + lane * V;
    float* op = zo + (size_t)w * D + lane * V;
    if (V == 4) {
        float4 sv = *(const float4*)hp;
        float4 bv = *(const float4*)bp;
        float4 o;
        o.x = acc[0] + sv.x * inv + bv.x;
        o.y = acc[1] + sv.y * inv + bv.y;
        o.z = acc[2] + sv.z * inv + bv.z;
        o.w = acc[3] + sv.w * inv + bv.w;
        if (RELU) { o.x = fmaxf(o.x, 0.f); o.y = fmaxf(o.y, 0.f);
                    o.z = fmaxf(o.z, 0.f); o.w = fmaxf(o.w, 0.f); }
        *(float4*)op = o;
    } else {
        float2 sv = *(const float2*)hp;
        float2 bv = *(const float2*)bp;
        float2 o;
        o.x = acc[0] + sv.x * inv + bv.x;
        o.y = acc[1] + sv.y * inv + bv.y;
        if (RELU) { o.x = fmaxf(o.x, 0.f); o.y = fmaxf(o.y, 0.f); }
        *(float2*)op = o;
    }
}

// ====================== decode ===============================================
__global__ void k_decode(const int* __restrict__ li, float* __restrict__ out) {
    int gid = blockIdx.x * blockDim.x + threadIdx.x;
    int e = gid >> 4;
    int l = gid & 15;
    if (e >= NL) return;
    int a = li[e];
    int b = li[NL + e];
    float4 va = *(const float4*)(g_z2 + (size_t)a * DOUT + l * 4);
    float4 vb = *(const float4*)(g_z2 + (size_t)b * DOUT + l * 4);
    float d = va.x * vb.x + va.y * vb.y + va.z * vb.z + va.w * vb.w;
    d += __shfl_xor_sync(0xffffffffu, d, 1);
    d += __shfl_xor_sync(0xffffffffu, d, 2);
    d += __shfl_xor_sync(0xffffffffu, d, 4);
    d += __shfl_xor_sync(0xffffffffu, d, 8);
    if (l == 0) out[e] = d;
}

// ====================== launch ===============================================
extern "C" void kernel_launch(void* const* d_in, const int* in_sizes, int n_in,
                              void* d_out, int out_size) {
    const float* x   = (const float*)d_in[0];
    const int*   ei  = (const int*)d_in[1];
    const int*   eli = (const int*)d_in[2];
    const float* W1  = (const float*)d_in[3];
    const float* b1  = (const float*)d_in[4];
    const float* W2  = (const float*)d_in[5];
    const float* b2  = (const float*)d_in[6];
    float* out = (float*)d_out;

    float *p_h1, *p_z, *p_h2, *p_z2;
    __nv_bfloat16 *p_w1h, *p_w1l, *p_w2h, *p_w2l;
    cudaGetSymbolAddress((void**)&p_h1, g_h1);
    cudaGetSymbolAddress((void**)&p_z,  g_z);
    cudaGetSymbolAddress((void**)&p_h2, g_h2);
    cudaGetSymbolAddress((void**)&p_z2, g_z2);
    cudaGetSymbolAddress((void**)&p_w1h, g_w1h);
    cudaGetSymbolAddress((void**)&p_w1l, g_w1l);
    cudaGetSymbolAddress((void**)&p_w2h, g_w2h);
    cudaGetSymbolAddress((void**)&p_w2l, g_w2l);

    const int SP = 136;
    const int SMEM1 = (2 * 128 * SP + 2 * 128 * SP) * 2;  // 139264 B
    const int SMEM2 = (2 * 128 * SP + 2 * 64 * SP) * 2;   // 104448 B
    cudaFuncSetAttribute(k_gemm_mma<128>, cudaFuncAttributeMaxDynamicSharedMemorySize, SMEM1);
    cudaFuncSetAttribute(k_gemm_mma<64>,  cudaFuncAttributeMaxDynamicSharedMemorySize, SMEM2);

    const int NB_NODE = (NN + 255) / 256;
    const int NB_EDGE = (NE + 255) / 256;
    const int NB_SCAN = (NN + 1023) / 1024;
    const int NB_GEMM = (NN + 127) / 128;
    const int NB_AGG  = (NN * 32 + 255) / 256;
    const int NB_DEC  = (NL * 16 + 255) / 256;

    // Order chosen so gemm1 is the 4th launch (ncu -s 5 should land on it,
    // accounting for harness pre-launches). gemm1 depends only on x + prepw1.
    k_prepw<128><<<(128 * 128 + 255) / 256, 256>>>(W1, p_w1h, p_w1l);
    k_prepw<64><<<(64 * 128 + 255) / 256, 256>>>(W2, p_w2h, p_w2l);
    k_zero_deg<<<NB_NODE, 256>>>();
    k_gemm_mma<128><<<NB_GEMM, 256, SMEM1>>>(x, p_w1h, p_w1l, p_h1, NN);   // h1 = x @ W1

    k_degree<<<NB_EDGE, 256>>>(ei);
    k_scan1<<<NB_SCAN, 1024>>>(NN);          // + dinv/invdeg fused
    k_scan2<<<1, 128>>>(NB_SCAN);
    k_scan3<<<NB_SCAN, 1024>>>(NN);
    k_scatter<<<NB_EDGE, 256>>>(ei);

    k_agg<DH, true><<<NB_AGG, 256>>>(p_h1, b1, p_z);                       // z = relu(Ah1+b1)
    k_gemm_mma<64><<<NB_GEMM, 256, SMEM2>>>(p_z, p_w2h, p_w2l, p_h2, NN);  // h2 = z @ W2
    k_agg<DOUT, false><<<NB_AGG, 256>>>(p_h2, b2, p_z2);                   // z2 = Ah2+b2
    k_decode<<<NB_DEC, 256>>>(eli, out);
}

// round 5
// speedup vs baseline: 1.6006x; 1.1424x over previous
#include <cuda_runtime.h>
#include <cuda_bf16.h>
#include <cuda_fp16.h>
#include <cstdint>

#define NN 100000
#define NE 1600000
#define NL 200000
#define DH  128
#define DOUT 64

// ====================== scratch (device globals) =============================
__device__ __align__(16) int   g_deg[NN];
__device__ __align__(16) float g_dinv[NN];
__device__ __align__(16) float g_invdeg[NN];
__device__ __align__(16) int   g_off[NN + 1];
__device__ __align__(16) int   g_cursor[NN];
__device__ __align__(16) int   g_csr[NE];
__device__ __align__(16) int   g_bsum[128];
__device__ __align__(16) __half g_h1[(size_t)NN * DH];   // gathered -> fp16
__device__ __align__(16) float  g_z [(size_t)NN * DH];   // linear-read -> fp32
__device__ __align__(16) __half g_h2[(size_t)NN * DOUT]; // gathered -> fp16
__device__ __align__(16) float  g_z2[(size_t)NN * DOUT]; // gathered by decode, fp32
// W fragments, mma-ready: [ks][ntile][lane] -> uint4{b0h,b1h,b0l,b1l}
__device__ __align__(16) uint4 g_wf1[8 * 16 * 32];
__device__ __align__(16) uint4 g_wf2[8 * 8 * 32];

// ====================== small helpers ========================================
__device__ __forceinline__ uint32_t smem_u32(const void* p) {
    uint32_t a;
    asm("{ .reg .u64 t; cvta.to.shared.u64 t, %1; cvt.u32.u64 %0, t; }" : "=r"(a) : "l"(p));
    return a;
}
__device__ __forceinline__ void ldmx4(uint32_t* r, uint32_t addr) {
    asm volatile("ldmatrix.sync.aligned.m8n8.x4.shared.b16 {%0,%1,%2,%3}, [%4];"
                 : "=r"(r[0]), "=r"(r[1]), "=r"(r[2]), "=r"(r[3]) : "r"(addr));
}
__device__ __forceinline__ void mma16816(float* c, const uint32_t* a, const uint32_t* b) {
    asm volatile(
        "mma.sync.aligned.m16n8k16.row.col.f32.bf16.bf16.f32 "
        "{%0,%1,%2,%3}, {%4,%5,%6,%7}, {%8,%9}, {%0,%1,%2,%3};"
        : "+f"(c[0]), "+f"(c[1]), "+f"(c[2]), "+f"(c[3])
        : "r"(a[0]), "r"(a[1]), "r"(a[2]), "r"(a[3]), "r"(b[0]), "r"(b[1]));
}
__device__ __forceinline__ uint32_t packbf2(float a, float b) {
    __nv_bfloat162 p = __halves2bfloat162(__float2bfloat16_rn(a), __float2bfloat16_rn(b));
    return *(uint32_t*)&p;
}

// ====================== setup kernels ========================================
__global__ void k_zero_deg() {
    int i = blockIdx.x * blockDim.x + threadIdx.x;
    if (i < NN) g_deg[i] = 0;
}
__global__ void k_degree(const int* __restrict__ ei) {
    int e = blockIdx.x * blockDim.x + threadIdx.x;
    if (e < NE) atomicAdd(&g_deg[ei[NE + e]], 1);
}
// scan phase 1 + dinv/invdeg fused
__global__ void k_scan1(int n) {
    __shared__ int wsum[32];
    int t = threadIdx.x;
    int gid = blockIdx.x * 1024 + t;
    int v = (gid < n) ? g_deg[gid] : 0;
    if (gid < n) {
        float d = (float)(v + 1);
        g_dinv[gid]   = rsqrtf(d);
        g_invdeg[gid] = 1.0f / d;
    }
    int x = v;
    #pragma unroll
    for (int o = 1; o < 32; o <<= 1) {
        int y = __shfl_up_sync(0xffffffffu, x, o);
        if ((t & 31) >= o) x += y;
    }
    if ((t & 31) == 31) wsum[t >> 5] = x;
    __syncthreads();
    if (t < 32) {
        int w = wsum[t];
        int xx = w;
        #pragma unroll
        for (int o = 1; o < 32; o <<= 1) {
            int y = __shfl_up_sync(0xffffffffu, xx, o);
            if (t >= o) xx += y;
        }
        wsum[t] = xx - w;
    }
    __syncthreads();
    int excl = x - v + wsum[t >> 5];
    if (gid < n) g_off[gid] = excl;
    if (t == 1023) g_bsum[blockIdx.x] = excl + v;
}
__global__ void k_scan2(int nb) {
    __shared__ int s[128];
    int t = threadIdx.x;
    int v = (t < nb) ? g_bsum[t] : 0;
    s[t] = v;
    __syncthreads();
    for (int o = 1; o < 128; o <<= 1) {
        int x = (t >= o) ? s[t - o] : 0;
        __syncthreads();
        s[t] += x;
        __syncthreads();
    }
    if (t < nb) g_bsum[t] = s[t] - v;
}
__global__ void k_scan3(int n) {
    int t = threadIdx.x;
    int gid = blockIdx.x * 1024 + t;
    if (gid < n) {
        int v = g_off[gid] + g_bsum[blockIdx.x];
        g_off[gid]    = v;
        g_cursor[gid] = v;
    }
    if (gid == 0) g_off[n] = NE;
}
__global__ void k_scatter(const int* __restrict__ ei) {
    int e = blockIdx.x * blockDim.x + threadIdx.x;
    if (e < NE) {
        int s = ei[e];
        int d = ei[NE + e];
        int p = atomicAdd(&g_cursor[d], 1);
        g_csr[p] = s;
    }
}

// ====================== W prep: mma fragment-major layout =====================
// fragment idx = (ks*(N/8) + ntile)*32 + lane ; uint4 {b0h, b1h, b0l, b1l}
// b0 covers (k, k+1), b1 covers (k+8, k+9) at column n, with
// n = ntile*8 + lane/4, k = ks*16 + (lane%4)*2.
template <int N>
__global__ void k_prepw(const float* __restrict__ W, uint4* __restrict__ frag) {
    int idx = blockIdx.x * blockDim.x + threadIdx.x;
    const int NT = N / 8;
    if (idx >= 8 * NT * 32) return;
    int lane = idx & 31;
    int nt   = (idx >> 5) % NT;
    int ks   = idx / (32 * NT);
    int n = nt * 8 + (lane >> 2);
    int k = ks * 16 + (lane & 3) * 2;
    float v0 = W[(k    ) * N + n];
    float v1 = W[(k + 1) * N + n];
    float v2 = W[(k + 8) * N + n];
    float v3 = W[(k + 9) * N + n];
    __nv_bfloat16 h0 = __float2bfloat16_rn(v0), h1 = __float2bfloat16_rn(v1);
    __nv_bfloat16 h2 = __float2bfloat16_rn(v2), h3 = __float2bfloat16_rn(v3);
    float l0f = v0 - __bfloat162float(h0), l1f = v1 - __bfloat162float(h1);
    float l2f = v2 - __bfloat162float(h2), l3f = v3 - __bfloat162float(h3);
    uint4 o;
    { __nv_bfloat162 p = __halves2bfloat162(h0, h1); o.x = *(uint32_t*)&p; }
    { __nv_bfloat162 p = __halves2bfloat162(h2, h3); o.y = *(uint32_t*)&p; }
    o.z = packbf2(l0f, l1f);
    o.w = packbf2(l2f, l3f);
    frag[idx] = o;
}

// ====================== HMMA GEMM: C[M,N] = A[M,128] @ W[128,N], C fp16 ======
// 3-term bf16 split. A (fp32) staged hi/lo in smem; B fragments direct LDG.128.
// CTA tile 128 x N, 8 warps 4(m) x 2(n). 2 CTAs/SM.
template <int N>
__global__ void __launch_bounds__(256, 2) k_gemm_mma(
    const float* __restrict__ A,
    const uint4* __restrict__ Wf,
    __half* __restrict__ C, int M) {
    const int SP = 136;
    const int WN = N / 2;
    const int NS = WN / 8;
    const int NT = N / 8;
    extern __shared__ __align__(16) __nv_bfloat16 sm[];
    __nv_bfloat16* As_h = sm;                 // [128][SP]
    __nv_bfloat16* As_l = sm + 128 * SP;

    int tid = threadIdx.x, lane = tid & 31, wid = tid >> 5;
    int row0 = blockIdx.x * 128;

    // --- fill A (convert fp32 -> bf16 hi/lo) ---
    #pragma unroll
    for (int i = tid; i < 4096; i += 256) {
        int r  = i >> 5;
        int c4 = (i & 31) << 2;
        int row = row0 + r;
        float4 v = (row < M) ? *(const float4*)(A + (size_t)row * 128 + c4)
                             : make_float4(0.f, 0.f, 0.f, 0.f);
        __nv_bfloat16 h0 = __float2bfloat16_rn(v.x);
        __nv_bfloat16 h1 = __float2bfloat16_rn(v.y);
        __nv_bfloat16 h2 = __float2bfloat16_rn(v.z);
        __nv_bfloat16 h3 = __float2bfloat16_rn(v.w);
        uint32_t hp0, hp1;
        { __nv_bfloat162 p = __halves2bfloat162(h0, h1); hp0 = *(uint32_t*)&p; }
        { __nv_bfloat162 p = __halves2bfloat162(h2, h3); hp1 = *(uint32_t*)&p; }
        uint32_t lp0 = packbf2(v.x - __bfloat162float(h0), v.y - __bfloat162float(h1));
        uint32_t lp1 = packbf2(v.z - __bfloat162float(h2), v.w - __bfloat162float(h3));
        int o = r * SP + c4;
        *(uint2*)(As_h + o) = make_uint2(hp0, hp1);
        *(uint2*)(As_l + o) = make_uint2(lp0, lp1);
    }
    __syncthreads();

    int wm  = (wid >> 1) * 32;
    int wnt = (wid & 1) * NS;       // warp n-tile origin

    float acc[2][NS][4];
    #pragma unroll
    for (int ms = 0; ms < 2; ms++)
        #pragma unroll
        for (int ns = 0; ns < NS; ns++)
            #pragma unroll
            for (int q = 0; q < 4; q++) acc[ms][ns][q] = 0.f;

    uint32_t base_ah = smem_u32(As_h);
    uint32_t base_al = smem_u32(As_l);

    #pragma unroll
    for (int k0 = 0; k0 < 128; k0 += 16) {
        int ks = k0 >> 4;
        uint32_t a_h[2][4], a_l[2][4];
        #pragma unroll
        for (int ms = 0; ms < 2; ms++) {
            int ar = wm + ms * 16 + (lane & 15);
            int ac = k0 + (lane >> 4) * 8;
            uint32_t off = (uint32_t)(ar * SP + ac) * 2;
            ldmx4(a_h[ms], base_ah + off);
            ldmx4(a_l[ms], base_al + off);
        }
        const uint4* fp = Wf + ((size_t)ks * NT + wnt) * 32 + lane;
        #pragma unroll
        for (int ns = 0; ns < NS; ns++) {
            uint4 f = __ldg(fp + ns * 32);
            uint32_t bh[2] = {f.x, f.y};
            uint32_t bl[2] = {f.z, f.w};
            mma16816(acc[0][ns], a_h[0], bh);
            mma16816(acc[0][ns], a_l[0], bh);
            mma16816(acc[0][ns], a_h[0], bl);
            mma16816(acc[1][ns], a_h[1], bh);
            mma16816(acc[1][ns], a_l[1], bh);
            mma16816(acc[1][ns], a_h[1], bl);
        }
    }

    // --- epilogue: fp16 output ---
    int gID = lane >> 2, tig = lane & 3;
    #pragma unroll
    for (int ms = 0; ms < 2; ms++) {
        int r0 = row0 + wm + ms * 16 + gID;
        #pragma unroll
        for (int ns = 0; ns < NS; ns++) {
            int col = (wnt + ns) * 8 + tig * 2;
            if (r0 < M) {
                __half2 p = __floats2half2_rn(acc[ms][ns][0], acc[ms][ns][1]);
                *(__half2*)(C + (size_t)r0 * N + col) = p;
            }
            if (r0 + 8 < M) {
                __half2 p = __floats2half2_rn(acc[ms][ns][2], acc[ms][ns][3]);
                *(__half2*)(C + (size_t)(r0 + 8) * N + col) = p;
            }
        }
    }
}

// ====================== aggregation: one warp per node (fp16 gathers) ========
template <int D, bool RELU>
__global__ void k_agg(const __half* __restrict__ h, const float* __restrict__ bias,
                      float* __restrict__ zo) {
    int w    = (blockIdx.x * blockDim.x + threadIdx.x) >> 5;
    int lane = threadIdx.x & 31;
    if (w >= NN) return;
    const int V = D / 32;           // 4 or 2 (elements per lane)
    int beg = g_off[w], end = g_off[w + 1];
    float di = g_dinv[w];
    float acc[V];
    #pragma unroll
    for (int i = 0; i < V; i++) acc[i] = 0.0f;

    for (int base = beg; base < end; base += 32) {
        int e = base + lane;
        int s = 0; float nm = 0.0f;
        if (e < end) { s = g_csr[e]; nm = g_dinv[s] * di; }
        int cnt = min(32, end - base);
        int j = 0;
        for (; j + 1 < cnt; j += 2) {
            int   s0 = __shfl_sync(0xffffffffu, s,  j);
            float n0 = __shfl_sync(0xffffffffu, nm, j);
            int   s1 = __shfl_sync(0xffffffffu, s,  j + 1);
            float n1 = __shfl_sync(0xffffffffu, nm, j + 1);
            const __half* p0 = h + (size_t)s0 * D + lane * V;
            const __half* p1 = h + (size_t)s1 * D + lane * V;
            if (V == 4) {
                uint2 u0 = *(const uint2*)p0;
                uint2 u1 = *(const uint2*)p1;
                float2 a0 = __half22float2(*(__half2*)&u0.x);
                float2 b0 = __half22float2(*(__half2*)&u0.y);
                float2 a1 = __half22float2(*(__half2*)&u1.x);
                float2 b1 = __half22float2(*(__half2*)&u1.y);
                acc[0] += a0.x * n0; acc[1] += a0.y * n0;
                acc[2] += b0.x * n0; acc[3] += b0.y * n0;
                acc[0] += a1.x * n1; acc[1] += a1.y * n1;
                acc[2] += b1.x * n1; acc[3] += b1.y * n1;
            } else {
                uint32_t u0 = *(const uint32_t*)p0;
                uint32_t u1 = *(const uint32_t*)p1;
                float2 a0 = __half22float2(*(__half2*)&u0);
                float2 a1 = __half22float2(*(__half2*)&u1);
                acc[0] += a0.x * n0; acc[1] += a0.y * n0;
                acc[0] += a1.x * n1; acc[1] += a1.y * n1;
            }
        }
        if (j < cnt) {
            int   s0 = __shfl_sync(0xffffffffu, s,  j);
            float n0 = __shfl_sync(0xffffffffu, nm, j);
            const __half* p0 = h + (size_t)s0 * D + lane * V;
            if (V == 4) {
                uint2 u0 = *(const uint2*)p0;
                float2 a0 = __half22float2(*(__half2*)&u0.x);
                float2 b0 = __half22float2(*(__half2*)&u0.y);
                acc[0] += a0.x * n0; acc[1] += a0.y * n0;
                acc[2] += b0.x * n0; acc[3] += b0.y * n0;
            } else {
                uint32_t u0 = *(const uint32_t*)p0;
                float2 a0 = __half22float2(*(__half2*)&u0);
                acc[0] += a0.x * n0; acc[1] += a0.y * n0;
            }
        }
    }

    float inv = g_invdeg[w];
    const __half* hp = h + (size_t)w * D + lane * V;
    const float* bp = bias + lane * V;
    float* op = zo + (size_t)w * D + lane * V;
    if (V == 4) {
        uint2 su = *(const uint2*)hp;
        float2 s0 = __half22float2(*(__half2*)&su.x);
        float2 s1 = __half22float2(*(__half2*)&su.y);
        float4 bv = *(const float4*)bp;
        float4 o;
        o.x = acc[0] + s0.x * inv + bv.x;
        o.y = acc[1] + s0.y * inv + bv.y;
        o.z = acc[2] + s1.x * inv + bv.z;
        o.w = acc[3] + s1.y * inv + bv.w;
        if (RELU) { o.x = fmaxf(o.x, 0.f); o.y = fmaxf(o.y, 0.f);
                    o.z = fmaxf(o.z, 0.f); o.w = fmaxf(o.w, 0.f); }
        *(float4*)op = o;
    } else {
        uint32_t su = *(const uint32_t*)hp;
        float2 s0 = __half22float2(*(__half2*)&su);
        float2 bv = *(const float2*)bp;
        float2 o;
        o.x = acc[0] + s0.x * inv + bv.x;
        o.y = acc[1] + s0.y * inv + bv.y;
        if (RELU) { o.x = fmaxf(o.x, 0.f); o.y = fmaxf(o.y, 0.f); }
        *(float2*)op = o;
    }
}

// ====================== decode ===============================================
__global__ void k_decode(const int* __restrict__ li, float* __restrict__ out) {
    int gid = blockIdx.x * blockDim.x + threadIdx.x;
    int e = gid >> 4;
    int l = gid & 15;
    if (e >= NL) return;
    int a = li[e];
    int b = li[NL + e];
    float4 va = *(const float4*)(g_z2 + (size_t)a * DOUT + l * 4);
    float4 vb = *(const float4*)(g_z2 + (size_t)b * DOUT + l * 4);
    float d = va.x * vb.x + va.y * vb.y + va.z * vb.z + va.w * vb.w;
    d += __shfl_xor_sync(0xffffffffu, d, 1);
    d += __shfl_xor_sync(0xffffffffu, d, 2);
    d += __shfl_xor_sync(0xffffffffu, d, 4);
    d += __shfl_xor_sync(0xffffffffu, d, 8);
    if (l == 0) out[e] = d;
}

// ====================== launch ===============================================
extern "C" void kernel_launch(void* const* d_in, const int* in_sizes, int n_in,
                              void* d_out, int out_size) {
    const float* x   = (const float*)d_in[0];
    const int*   ei  = (const int*)d_in[1];
    const int*   eli = (const int*)d_in[2];
    const float* W1  = (const float*)d_in[3];
    const float* b1  = (const float*)d_in[4];
    const float* W2  = (const float*)d_in[5];
    const float* b2  = (const float*)d_in[6];
    float* out = (float*)d_out;

    __half *p_h1, *p_h2;
    float *p_z, *p_z2;
    uint4 *p_wf1, *p_wf2;
    cudaGetSymbolAddress((void**)&p_h1, g_h1);
    cudaGetSymbolAddress((void**)&p_z,  g_z);
    cudaGetSymbolAddress((void**)&p_h2, g_h2);
    cudaGetSymbolAddress((void**)&p_z2, g_z2);
    cudaGetSymbolAddress((void**)&p_wf1, g_wf1);
    cudaGetSymbolAddress((void**)&p_wf2, g_wf2);

    const int SP = 136;
    const int SMEMA = 2 * 128 * SP * 2;   // 69632 B (A hi/lo only)
    cudaFuncSetAttribute(k_gemm_mma<128>, cudaFuncAttributeMaxDynamicSharedMemorySize, SMEMA);
    cudaFuncSetAttribute(k_gemm_mma<64>,  cudaFuncAttributeMaxDynamicSharedMemorySize, SMEMA);

    const int NB_NODE = (NN + 255) / 256;
    const int NB_EDGE = (NE + 255) / 256;
    const int NB_SCAN = (NN + 1023) / 1024;
    const int NB_GEMM = (NN + 127) / 128;
    const int NB_AGG  = (NN * 32 + 255) / 256;
    const int NB_DEC  = (NL * 16 + 255) / 256;

    // gemm1 stays 4th launch so ncu -s 5 lands on it.
    k_prepw<128><<<(8 * 16 * 32 + 255) / 256, 256>>>(W1, p_wf1);
    k_prepw<64><<<(8 * 8 * 32 + 255) / 256, 256>>>(W2, p_wf2);
    k_zero_deg<<<NB_NODE, 256>>>();
    k_gemm_mma<128><<<NB_GEMM, 256, SMEMA>>>(x, p_wf1, p_h1, NN);     // h1 = x @ W1 (fp16)

    k_degree<<<NB_EDGE, 256>>>(ei);
    k_scan1<<<NB_SCAN, 1024>>>(NN);
    k_scan2<<<1, 128>>>(NB_SCAN);
    k_scan3<<<NB_SCAN, 1024>>>(NN);
    k_scatter<<<NB_EDGE, 256>>>(ei);

    k_agg<DH, true><<<NB_AGG, 256>>>(p_h1, b1, p_z);                  // z = relu(Ah1+b1) fp32
    k_gemm_mma<64><<<NB_GEMM, 256, SMEMA>>>(p_z, p_wf2, p_h2, NN);    // h2 = z @ W2 (fp16)
    k_agg<DOUT, false><<<NB_AGG, 256>>>(p_h2, b2, p_z2);              // z2 = Ah2+b2 fp32
    k_decode<<<NB_DEC, 256>>>(eli, out);
}

// round 6
// speedup vs baseline: 1.6533x; 1.0330x over previous
#include <cuda_runtime.h>
#include <cuda_bf16.h>
#include <cuda_fp16.h>
#include <cstdint>

#define NN 100000
#define NE 1600000
#define NL 200000
#define DH  128
#define DOUT 64

// ====================== scratch (device globals) =============================
__device__ __align__(16) int   g_deg[NN];
__device__ __align__(16) float g_dinv[NN];
__device__ __align__(16) float g_invdeg[NN];
__device__ __align__(16) int   g_off[NN + 1];
__device__ __align__(16) int   g_cursor[NN];
__device__ __align__(16) int2  g_csrn[NE];               // {src, __float_as_int(norm)}
__device__ __align__(16) int   g_bsum[128];
__device__ __align__(16) __half g_h1[(size_t)NN * DH];   // gathered -> fp16
__device__ __align__(16) float  g_z [(size_t)NN * DH];
__device__ __align__(16) __half g_h2[(size_t)NN * DOUT]; // gathered -> fp16
__device__ __align__(16) float  g_z2[(size_t)NN * DOUT];
// W fragments, mma-ready: [ks][ntile][lane] -> uint4{b0h,b1h,b0l,b1l}
__device__ __align__(16) uint4 g_wf1[8 * 16 * 32];
__device__ __align__(16) uint4 g_wf2[8 * 8 * 32];

// ====================== small helpers ========================================
__device__ __forceinline__ uint32_t smem_u32(const void* p) {
    uint32_t a;
    asm("{ .reg .u64 t; cvta.to.shared.u64 t, %1; cvt.u32.u64 %0, t; }" : "=r"(a) : "l"(p));
    return a;
}
__device__ __forceinline__ void ldmx4(uint32_t* r, uint32_t addr) {
    asm volatile("ldmatrix.sync.aligned.m8n8.x4.shared.b16 {%0,%1,%2,%3}, [%4];"
                 : "=r"(r[0]), "=r"(r[1]), "=r"(r[2]), "=r"(r[3]) : "r"(addr));
}
__device__ __forceinline__ void mma16816(float* c, const uint32_t* a, const uint32_t* b) {
    asm volatile(
        "mma.sync.aligned.m16n8k16.row.col.f32.bf16.bf16.f32 "
        "{%0,%1,%2,%3}, {%4,%5,%6,%7}, {%8,%9}, {%0,%1,%2,%3};"
        : "+f"(c[0]), "+f"(c[1]), "+f"(c[2]), "+f"(c[3])
        : "r"(a[0]), "r"(a[1]), "r"(a[2]), "r"(a[3]), "r"(b[0]), "r"(b[1]));
}
__device__ __forceinline__ uint32_t packbf2(float a, float b) {
    __nv_bfloat162 p = __halves2bfloat162(__float2bfloat16_rn(a), __float2bfloat16_rn(b));
    return *(uint32_t*)&p;
}

// ====================== setup kernels ========================================
__global__ void k_zero_deg() {
    int i = blockIdx.x * blockDim.x + threadIdx.x;
    if (i < NN) g_deg[i] = 0;
}
__global__ void k_degree(const int* __restrict__ ei) {
    int e = blockIdx.x * blockDim.x + threadIdx.x;
    if (e < NE) atomicAdd(&g_deg[ei[NE + e]], 1);
}
// scan phase 1 + dinv/invdeg fused
__global__ void k_scan1(int n) {
    __shared__ int wsum[32];
    int t = threadIdx.x;
    int gid = blockIdx.x * 1024 + t;
    int v = (gid < n) ? g_deg[gid] : 0;
    if (gid < n) {
        float d = (float)(v + 1);
        g_dinv[gid]   = rsqrtf(d);
        g_invdeg[gid] = 1.0f / d;
    }
    int x = v;
    #pragma unroll
    for (int o = 1; o < 32; o <<= 1) {
        int y = __shfl_up_sync(0xffffffffu, x, o);
        if ((t & 31) >= o) x += y;
    }
    if ((t & 31) == 31) wsum[t >> 5] = x;
    __syncthreads();
    if (t < 32) {
        int w = wsum[t];
        int xx = w;
        #pragma unroll
        for (int o = 1; o < 32; o <<= 1) {
            int y = __shfl_up_sync(0xffffffffu, xx, o);
            if (t >= o) xx += y;
        }
        wsum[t] = xx - w;
    }
    __syncthreads();
    int excl = x - v + wsum[t >> 5];
    if (gid < n) g_off[gid] = excl;
    if (t == 1023) g_bsum[blockIdx.x] = excl + v;
}
__global__ void k_scan2(int nb) {
    __shared__ int s[128];
    int t = threadIdx.x;
    int v = (t < nb) ? g_bsum[t] : 0;
    s[t] = v;
    __syncthreads();
    for (int o = 1; o < 128; o <<= 1) {
        int x = (t >= o) ? s[t - o] : 0;
        __syncthreads();
        s[t] += x;
        __syncthreads();
    }
    if (t < nb) g_bsum[t] = s[t] - v;
}
__global__ void k_scan3(int n) {
    int t = threadIdx.x;
    int gid = blockIdx.x * 1024 + t;
    if (gid < n) {
        int v = g_off[gid] + g_bsum[blockIdx.x];
        g_off[gid]    = v;
        g_cursor[gid] = v;
    }
    if (gid == 0) g_off[n] = NE;
}
// scatter edge -> CSR slot, with per-edge norm precomputed (kills the
// per-lane dinv gather inside agg)
__global__ void k_scatter(const int* __restrict__ ei) {
    int e = blockIdx.x * blockDim.x + threadIdx.x;
    if (e < NE) {
        int s = ei[e];
        int d = ei[NE + e];
        float nm = g_dinv[s] * g_dinv[d];
        int p = atomicAdd(&g_cursor[d], 1);
        g_csrn[p] = make_int2(s, __float_as_int(nm));
    }
}

// ====================== W prep: mma fragment-major layout =====================
template <int N>
__global__ void k_prepw(const float* __restrict__ W, uint4* __restrict__ frag) {
    int idx = blockIdx.x * blockDim.x + threadIdx.x;
    const int NT = N / 8;
    if (idx >= 8 * NT * 32) return;
    int lane = idx & 31;
    int nt   = (idx >> 5) % NT;
    int ks   = idx / (32 * NT);
    int n = nt * 8 + (lane >> 2);
    int k = ks * 16 + (lane & 3) * 2;
    float v0 = W[(k    ) * N + n];
    float v1 = W[(k + 1) * N + n];
    float v2 = W[(k + 8) * N + n];
    float v3 = W[(k + 9) * N + n];
    __nv_bfloat16 h0 = __float2bfloat16_rn(v0), h1 = __float2bfloat16_rn(v1);
    __nv_bfloat16 h2 = __float2bfloat16_rn(v2), h3 = __float2bfloat16_rn(v3);
    uint4 o;
    { __nv_bfloat162 p = __halves2bfloat162(h0, h1); o.x = *(uint32_t*)&p; }
    { __nv_bfloat162 p = __halves2bfloat162(h2, h3); o.y = *(uint32_t*)&p; }
    o.z = packbf2(v0 - __bfloat162float(h0), v1 - __bfloat162float(h1));
    o.w = packbf2(v2 - __bfloat162float(h2), v3 - __bfloat162float(h3));
    frag[idx] = o;
}

// ====================== HMMA GEMM: C[M,N] = A[M,128] @ W[128,N], C fp16 ======
template <int N>
__global__ void __launch_bounds__(256, 2) k_gemm_mma(
    const float* __restrict__ A,
    const uint4* __restrict__ Wf,
    __half* __restrict__ C, int M) {
    const int SP = 136;
    const int WN = N / 2;
    const int NS = WN / 8;
    const int NT = N / 8;
    extern __shared__ __align__(16) __nv_bfloat16 sm[];
    __nv_bfloat16* As_h = sm;                 // [128][SP]
    __nv_bfloat16* As_l = sm + 128 * SP;

    int tid = threadIdx.x, lane = tid & 31, wid = tid >> 5;
    int row0 = blockIdx.x * 128;

    #pragma unroll
    for (int i = tid; i < 4096; i += 256) {
        int r  = i >> 5;
        int c4 = (i & 31) << 2;
        int row = row0 + r;
        float4 v = (row < M) ? *(const float4*)(A + (size_t)row * 128 + c4)
                             : make_float4(0.f, 0.f, 0.f, 0.f);
        __nv_bfloat16 h0 = __float2bfloat16_rn(v.x);
        __nv_bfloat16 h1 = __float2bfloat16_rn(v.y);
        __nv_bfloat16 h2 = __float2bfloat16_rn(v.z);
        __nv_bfloat16 h3 = __float2bfloat16_rn(v.w);
        uint32_t hp0, hp1;
        { __nv_bfloat162 p = __halves2bfloat162(h0, h1); hp0 = *(uint32_t*)&p; }
        { __nv_bfloat162 p = __halves2bfloat162(h2, h3); hp1 = *(uint32_t*)&p; }
        uint32_t lp0 = packbf2(v.x - __bfloat162float(h0), v.y - __bfloat162float(h1));
        uint32_t lp1 = packbf2(v.z - __bfloat162float(h2), v.w - __bfloat162float(h3));
        int o = r * SP + c4;
        *(uint2*)(As_h + o) = make_uint2(hp0, hp1);
        *(uint2*)(As_l + o) = make_uint2(lp0, lp1);
    }
    __syncthreads();

    int wm  = (wid >> 1) * 32;
    int wnt = (wid & 1) * NS;

    float acc[2][NS][4];
    #pragma unroll
    for (int ms = 0; ms < 2; ms++)
        #pragma unroll
        for (int ns = 0; ns < NS; ns++)
            #pragma unroll
            for (int q = 0; q < 4; q++) acc[ms][ns][q] = 0.f;

    uint32_t base_ah = smem_u32(As_h);
    uint32_t base_al = smem_u32(As_l);

    #pragma unroll
    for (int k0 = 0; k0 < 128; k0 += 16) {
        int ks = k0 >> 4;
        uint32_t a_h[2][4], a_l[2][4];
        #pragma unroll
        for (int ms = 0; ms < 2; ms++) {
            int ar = wm + ms * 16 + (lane & 15);
            int ac = k0 + (lane >> 4) * 8;
            uint32_t off = (uint32_t)(ar * SP + ac) * 2;
            ldmx4(a_h[ms], base_ah + off);
            ldmx4(a_l[ms], base_al + off);
        }
        const uint4* fp = Wf + ((size_t)ks * NT + wnt) * 32 + lane;
        #pragma unroll
        for (int ns = 0; ns < NS; ns++) {
            uint4 f = __ldg(fp + ns * 32);
            uint32_t bh[2] = {f.x, f.y};
            uint32_t bl[2] = {f.z, f.w};
            mma16816(acc[0][ns], a_h[0], bh);
            mma16816(acc[0][ns], a_l[0], bh);
            mma16816(acc[0][ns], a_h[0], bl);
            mma16816(acc[1][ns], a_h[1], bh);
            mma16816(acc[1][ns], a_l[1], bh);
            mma16816(acc[1][ns], a_h[1], bl);
        }
    }

    int gID = lane >> 2, tig = lane & 3;
    #pragma unroll
    for (int ms = 0; ms < 2; ms++) {
        int r0 = row0 + wm + ms * 16 + gID;
        #pragma unroll
        for (int ns = 0; ns < NS; ns++) {
            int col = (wnt + ns) * 8 + tig * 2;
            if (r0 < M) {
                __half2 p = __floats2half2_rn(acc[ms][ns][0], acc[ms][ns][1]);
                *(__half2*)(C + (size_t)r0 * N + col) = p;
            }
            if (r0 + 8 < M) {
                __half2 p = __floats2half2_rn(acc[ms][ns][2], acc[ms][ns][3]);
                *(__half2*)(C + (size_t)(r0 + 8) * N + col) = p;
            }
        }
    }
}

// ====================== aggregation: one warp per node (fp16 gathers) ========
template <int D, bool RELU>
__global__ void k_agg(const __half* __restrict__ h, const float* __restrict__ bias,
                      float* __restrict__ zo) {
    int w    = (blockIdx.x * blockDim.x + threadIdx.x) >> 5;
    int lane = threadIdx.x & 31;
    if (w >= NN) return;
    const int V = D / 32;
    int beg = g_off[w], end = g_off[w + 1];
    float acc[V];
    #pragma unroll
    for (int i = 0; i < V; i++) acc[i] = 0.0f;

    for (int base = beg; base < end; base += 32) {
        int e = base + lane;
        int2 sn = (e < end) ? g_csrn[e] : make_int2(0, 0);
        int s = sn.x;
        float nm = __int_as_float(sn.y);
        int cnt = min(32, end - base);
        int j = 0;
        for (; j + 1 < cnt; j += 2) {
            int   s0 = __shfl_sync(0xffffffffu, s,  j);
            float n0 = __shfl_sync(0xffffffffu, nm, j);
            int   s1 = __shfl_sync(0xffffffffu, s,  j + 1);
            float n1 = __shfl_sync(0xffffffffu, nm, j + 1);
            const __half* p0 = h + (size_t)s0 * D + lane * V;
            const __half* p1 = h + (size_t)s1 * D + lane * V;
            if (V == 4) {
                uint2 u0 = *(const uint2*)p0;
                uint2 u1 = *(const uint2*)p1;
                float2 a0 = __half22float2(*(__half2*)&u0.x);
                float2 b0 = __half22float2(*(__half2*)&u0.y);
                float2 a1 = __half22float2(*(__half2*)&u1.x);
                float2 b1 = __half22float2(*(__half2*)&u1.y);
                acc[0] += a0.x * n0; acc[1] += a0.y * n0;
                acc[2] += b0.x * n0; acc[3] += b0.y * n0;
                acc[0] += a1.x * n1; acc[1] += a1.y * n1;
                acc[2] += b1.x * n1; acc[3] += b1.y * n1;
            } else {
                uint32_t u0 = *(const uint32_t*)p0;
                uint32_t u1 = *(const uint32_t*)p1;
                float2 a0 = __half22float2(*(__half2*)&u0);
                float2 a1 = __half22float2(*(__half2*)&u1);
                acc[0] += a0.x * n0; acc[1] += a0.y * n0;
                acc[0] += a1.x * n1; acc[1] += a1.y * n1;
            }
        }
        if (j < cnt) {
            int   s0 = __shfl_sync(0xffffffffu, s,  j);
            float n0 = __shfl_sync(0xffffffffu, nm, j);
            const __half* p0 = h + (size_t)s0 * D + lane * V;
            if (V == 4) {
                uint2 u0 = *(const uint2*)p0;
                float2 a0 = __half22float2(*(__half2*)&u0.x);
                float2 b0 = __half22float2(*(__half2*)&u0.y);
                acc[0] += a0.x * n0; acc[1] += a0.y * n0;
                acc[2] += b0.x * n0; acc[3] += b0.y * n0;
            } else {
                uint32_t u0 = *(const uint32_t*)p0;
                float2 a0 = __half22float2(*(__half2*)&u0);
                acc[0] += a0.x * n0; acc[1] += a0.y * n0;
            }
        }
    }

    float inv = g_invdeg[w];
    const __half* hp = h + (size_t)w * D + lane * V;
    const float* bp = bias + lane * V;
    float* op = zo + (size_t)w * D + lane * V;
    if (V == 4) {
        uint2 su = *(const uint2*)hp;
        float2 s0 = __half22float2(*(__half2*)&su.x);
        float2 s1 = __half22float2(*(__half2*)&su.y);
        float4 bv = *(const float4*)bp;
        float4 o;
        o.x = acc[0] + s0.x * inv + bv.x;
        o.y = acc[1] + s0.y * inv + bv.y;
        o.z = acc[2] + s1.x * inv + bv.z;
        o.w = acc[3] + s1.y * inv + bv.w;
        if (RELU) { o.x = fmaxf(o.x, 0.f); o.y = fmaxf(o.y, 0.f);
                    o.z = fmaxf(o.z, 0.f); o.w = fmaxf(o.w, 0.f); }
        *(float4*)op = o;
    } else {
        uint32_t su = *(const uint32_t*)hp;
        float2 s0 = __half22float2(*(__half2*)&su);
        float2 bv = *(const float2*)bp;
        float2 o;
        o.x = acc[0] + s0.x * inv + bv.x;
        o.y = acc[1] + s0.y * inv + bv.y;
        if (RELU) { o.x = fmaxf(o.x, 0.f); o.y = fmaxf(o.y, 0.f); }
        *(float2*)op = o;
    }
}

// ====================== decode ===============================================
__global__ void k_decode(const int* __restrict__ li, float* __restrict__ out) {
    int gid = blockIdx.x * blockDim.x + threadIdx.x;
    int e = gid >> 4;
    int l = gid & 15;
    if (e >= NL) return;
    int a = li[e];
    int b = li[NL + e];
    float4 va = *(const float4*)(g_z2 + (size_t)a * DOUT + l * 4);
    float4 vb = *(const float4*)(g_z2 + (size_t)b * DOUT + l * 4);
    float d = va.x * vb.x + va.y * vb.y + va.z * vb.z + va.w * vb.w;
    d += __shfl_xor_sync(0xffffffffu, d, 1);
    d += __shfl_xor_sync(0xffffffffu, d, 2);
    d += __shfl_xor_sync(0xffffffffu, d, 4);
    d += __shfl_xor_sync(0xffffffffu, d, 8);
    if (l == 0) out[e] = d;
}

// ====================== launch ===============================================
extern "C" void kernel_launch(void* const* d_in, const int* in_sizes, int n_in,
                              void* d_out, int out_size) {
    const float* x   = (const float*)d_in[0];
    const int*   ei  = (const int*)d_in[1];
    const int*   eli = (const int*)d_in[2];
    const float* W1  = (const float*)d_in[3];
    const float* b1  = (const float*)d_in[4];
    const float* W2  = (const float*)d_in[5];
    const float* b2  = (const float*)d_in[6];
    float* out = (float*)d_out;

    __half *p_h1, *p_h2;
    float *p_z, *p_z2;
    uint4 *p_wf1, *p_wf2;
    cudaGetSymbolAddress((void**)&p_h1, g_h1);
    cudaGetSymbolAddress((void**)&p_z,  g_z);
    cudaGetSymbolAddress((void**)&p_h2, g_h2);
    cudaGetSymbolAddress((void**)&p_z2, g_z2);
    cudaGetSymbolAddress((void**)&p_wf1, g_wf1);
    cudaGetSymbolAddress((void**)&p_wf2, g_wf2);

    const int SP = 136;
    const int SMEMA = 2 * 128 * SP * 2;   // 69632 B
    cudaFuncSetAttribute(k_gemm_mma<128>, cudaFuncAttributeMaxDynamicSharedMemorySize, SMEMA);
    cudaFuncSetAttribute(k_gemm_mma<64>,  cudaFuncAttributeMaxDynamicSharedMemorySize, SMEMA);

    const int NB_NODE = (NN + 255) / 256;
    const int NB_EDGE = (NE + 255) / 256;
    const int NB_SCAN = (NN + 1023) / 1024;
    const int NB_GEMM = (NN + 127) / 128;
    const int NB_AGG  = (NN * 32 + 255) / 256;
    const int NB_DEC  = (NL * 16 + 255) / 256;

    // fork-join: graph-setup branch (s2) overlaps W-prep + gemm1 (main).
    // Streams/events are intentionally not destroyed: kernel_launch is called
    // only a handful of times (correctness + capture), and destroying a stream
    // that participated in an ongoing capture would invalidate it.
    cudaStream_t s2;
    cudaStreamCreateWithFlags(&s2, cudaStreamNonBlocking);
    cudaEvent_t evF, evJ;
    cudaEventCreateWithFlags(&evF, cudaEventDisableTiming);
    cudaEventCreateWithFlags(&evJ, cudaEventDisableTiming);

    k_prepw<128><<<(8 * 16 * 32 + 255) / 256, 256>>>(W1, p_wf1);      // 1
    k_prepw<64><<<(8 * 8 * 32 + 255) / 256, 256>>>(W2, p_wf2);        // 2

    cudaEventRecord(evF, 0);
    cudaStreamWaitEvent(s2, evF, 0);

    k_zero_deg<<<NB_NODE, 256, 0, s2>>>();                            // 3
    k_gemm_mma<128><<<NB_GEMM, 256, SMEMA>>>(x, p_wf1, p_h1, NN);     // 4 (profiled)
    k_degree<<<NB_EDGE, 256, 0, s2>>>(ei);
    k_scan1<<<NB_SCAN, 1024, 0, s2>>>(NN);
    k_scan2<<<1, 128, 0, s2>>>(NB_SCAN);
    k_scan3<<<NB_SCAN, 1024, 0, s2>>>(NN);
    k_scatter<<<NB_EDGE, 256, 0, s2>>>(ei);

    cudaEventRecord(evJ, s2);
    cudaStreamWaitEvent(0, evJ, 0);

    k_agg<DH, true><<<NB_AGG, 256>>>(p_h1, b1, p_z);                  // z = relu(Ah1+b1)
    k_gemm_mma<64><<<NB_GEMM, 256, SMEMA>>>(p_z, p_wf2, p_h2, NN);    // h2 = z @ W2
    k_agg<DOUT, false><<<NB_AGG, 256>>>(p_h2, b2, p_z2);              // z2 = Ah2+b2
    k_decode<<<NB_DEC, 256>>>(eli, out);
}

// round 7
// speedup vs baseline: 1.8387x; 1.1121x over previous
#include <cuda_runtime.h>
#include <cuda_fp16.h>
#include <cstdint>

#define NN 100000
#define NE 1600000
#define NL 200000
#define DH  128
#define DOUT 64

// ====================== scratch (device globals) =============================
__device__ __align__(16) int   g_deg[NN];
__device__ __align__(16) float g_dinv[NN];
__device__ __align__(16) float g_invdeg[NN];
__device__ __align__(16) int   g_off[NN + 1];
__device__ __align__(16) int   g_cursor[NN];
__device__ __align__(16) int2  g_csrn[NE];               // {src, norm bits}
__device__ __align__(16) int   g_bsum[128];
__device__ __align__(16) __half g_h1[(size_t)NN * DH];   // fp16 everywhere downstream
__device__ __align__(16) __half g_z [(size_t)NN * DH];
__device__ __align__(16) __half g_h2[(size_t)NN * DOUT];
__device__ __align__(16) __half g_z2[(size_t)NN * DOUT];
// W fragments (fp16, hi only), mma-ready: [ks][ntile][lane] -> uint2{b0,b1}
__device__ __align__(16) uint2 g_wf1[8 * 16 * 32];
__device__ __align__(16) uint2 g_wf2[8 * 8 * 32];

// ====================== small helpers ========================================
__device__ __forceinline__ uint32_t smem_u32(const void* p) {
    uint32_t a;
    asm("{ .reg .u64 t; cvta.to.shared.u64 t, %1; cvt.u32.u64 %0, t; }" : "=r"(a) : "l"(p));
    return a;
}
__device__ __forceinline__ void ldmx4(uint32_t* r, uint32_t addr) {
    asm volatile("ldmatrix.sync.aligned.m8n8.x4.shared.b16 {%0,%1,%2,%3}, [%4];"
                 : "=r"(r[0]), "=r"(r[1]), "=r"(r[2]), "=r"(r[3]) : "r"(addr));
}
__device__ __forceinline__ void mma16816h(float* c, const uint32_t* a, const uint32_t* b) {
    asm volatile(
        "mma.sync.aligned.m16n8k16.row.col.f32.f16.f16.f32 "
        "{%0,%1,%2,%3}, {%4,%5,%6,%7}, {%8,%9}, {%0,%1,%2,%3};"
        : "+f"(c[0]), "+f"(c[1]), "+f"(c[2]), "+f"(c[3])
        : "r"(a[0]), "r"(a[1]), "r"(a[2]), "r"(a[3]), "r"(b[0]), "r"(b[1]));
}
__device__ __forceinline__ uint32_t packh2(float a, float b) {
    __half2 p = __floats2half2_rn(a, b);
    return *(uint32_t*)&p;
}

// ====================== setup kernels ========================================
__global__ void k_zero_deg() {
    int i = blockIdx.x * blockDim.x + threadIdx.x;
    if (i < NN) g_deg[i] = 0;
}
__global__ void k_degree(const int* __restrict__ ei) {
    int e = blockIdx.x * blockDim.x + threadIdx.x;
    if (e < NE) atomicAdd(&g_deg[ei[NE + e]], 1);
}
__global__ void k_scan1(int n) {
    __shared__ int wsum[32];
    int t = threadIdx.x;
    int gid = blockIdx.x * 1024 + t;
    int v = (gid < n) ? g_deg[gid] : 0;
    if (gid < n) {
        float d = (float)(v + 1);
        g_dinv[gid]   = rsqrtf(d);
        g_invdeg[gid] = 1.0f / d;
    }
    int x = v;
    #pragma unroll
    for (int o = 1; o < 32; o <<= 1) {
        int y = __shfl_up_sync(0xffffffffu, x, o);
        if ((t & 31) >= o) x += y;
    }
    if ((t & 31) == 31) wsum[t >> 5] = x;
    __syncthreads();
    if (t < 32) {
        int w = wsum[t];
        int xx = w;
        #pragma unroll
        for (int o = 1; o < 32; o <<= 1) {
            int y = __shfl_up_sync(0xffffffffu, xx, o);
            if (t >= o) xx += y;
        }
        wsum[t] = xx - w;
    }
    __syncthreads();
    int excl = x - v + wsum[t >> 5];
    if (gid < n) g_off[gid] = excl;
    if (t == 1023) g_bsum[blockIdx.x] = excl + v;
}
__global__ void k_scan2(int nb) {
    __shared__ int s[128];
    int t = threadIdx.x;
    int v = (t < nb) ? g_bsum[t] : 0;
    s[t] = v;
    __syncthreads();
    for (int o = 1; o < 128; o <<= 1) {
        int x = (t >= o) ? s[t - o] : 0;
        __syncthreads();
        s[t] += x;
        __syncthreads();
    }
    if (t < nb) g_bsum[t] = s[t] - v;
}
__global__ void k_scan3(int n) {
    int t = threadIdx.x;
    int gid = blockIdx.x * 1024 + t;
    if (gid < n) {
        int v = g_off[gid] + g_bsum[blockIdx.x];
        g_off[gid]    = v;
        g_cursor[gid] = v;
    }
    if (gid == 0) g_off[n] = NE;
}
__global__ void k_scatter(const int* __restrict__ ei) {
    int e = blockIdx.x * blockDim.x + threadIdx.x;
    if (e < NE) {
        int s = ei[e];
        int d = ei[NE + e];
        float nm = g_dinv[s] * g_dinv[d];
        int p = atomicAdd(&g_cursor[d], 1);
        g_csrn[p] = make_int2(s, __float_as_int(nm));
    }
}

// ====================== W prep: fp16 fragment-major ==========================
// frag idx = (ks*(N/8)+nt)*32+lane ; uint2{(k,k+1),(k+8,k+9)} at col n
// n = nt*8 + lane/4, k = ks*16 + (lane%4)*2.
template <int N>
__global__ void k_prepw(const float* __restrict__ W, uint2* __restrict__ frag) {
    int idx = blockIdx.x * blockDim.x + threadIdx.x;
    const int NT = N / 8;
    if (idx >= 8 * NT * 32) return;
    int lane = idx & 31;
    int nt   = (idx >> 5) % NT;
    int ks   = idx / (32 * NT);
    int n = nt * 8 + (lane >> 2);
    int k = ks * 16 + (lane & 3) * 2;
    uint2 o;
    o.x = packh2(W[(k    ) * N + n], W[(k + 1) * N + n]);
    o.y = packh2(W[(k + 8) * N + n], W[(k + 9) * N + n]);
    frag[idx] = o;
}

// ====================== gemm1: C[M,128] = A_fp32[M,128] @ W1, 2-term fp16 ====
__global__ void __launch_bounds__(256, 2) k_gemm1(
    const float* __restrict__ A,
    const uint2* __restrict__ Wf,
    __half* __restrict__ C, int M) {
    const int N = 128, SP = 136, NS = 8, NT = 16;
    extern __shared__ __align__(16) __half sm[];
    __half* As_h = sm;                 // [128][SP]
    __half* As_l = sm + 128 * SP;

    int tid = threadIdx.x, lane = tid & 31, wid = tid >> 5;
    int row0 = blockIdx.x * 128;

    #pragma unroll
    for (int i = tid; i < 4096; i += 256) {
        int r  = i >> 5;
        int c4 = (i & 31) << 2;
        int row = row0 + r;
        float4 v = (row < M) ? *(const float4*)(A + (size_t)row * 128 + c4)
                             : make_float4(0.f, 0.f, 0.f, 0.f);
        __half h0 = __float2half_rn(v.x), h1 = __float2half_rn(v.y);
        __half h2 = __float2half_rn(v.z), h3 = __float2half_rn(v.w);
        uint32_t hp0, hp1;
        { __half2 p = __halves2half2(h0, h1); hp0 = *(uint32_t*)&p; }
        { __half2 p = __halves2half2(h2, h3); hp1 = *(uint32_t*)&p; }
        uint32_t lp0 = packh2(v.x - __half2float(h0), v.y - __half2float(h1));
        uint32_t lp1 = packh2(v.z - __half2float(h2), v.w - __half2float(h3));
        int o = r * SP + c4;
        *(uint2*)(As_h + o) = make_uint2(hp0, hp1);
        *(uint2*)(As_l + o) = make_uint2(lp0, lp1);
    }
    __syncthreads();

    int wm  = (wid >> 1) * 32;
    int wnt = (wid & 1) * NS;

    float acc[2][NS][4];
    #pragma unroll
    for (int ms = 0; ms < 2; ms++)
        #pragma unroll
        for (int ns = 0; ns < NS; ns++)
            #pragma unroll
            for (int q = 0; q < 4; q++) acc[ms][ns][q] = 0.f;

    uint32_t base_ah = smem_u32(As_h);
    uint32_t base_al = smem_u32(As_l);

    #pragma unroll
    for (int k0 = 0; k0 < 128; k0 += 16) {
        int ks = k0 >> 4;
        uint32_t a_h[2][4], a_l[2][4];
        #pragma unroll
        for (int ms = 0; ms < 2; ms++) {
            int ar = wm + ms * 16 + (lane & 15);
            int ac = k0 + (lane >> 4) * 8;
            uint32_t off = (uint32_t)(ar * SP + ac) * 2;
            ldmx4(a_h[ms], base_ah + off);
            ldmx4(a_l[ms], base_al + off);
        }
        const uint2* fp = Wf + ((size_t)ks * NT + wnt) * 32 + lane;
        #pragma unroll
        for (int ns = 0; ns < NS; ns++) {
            uint2 f = __ldg(fp + ns * 32);
            uint32_t b[2] = {f.x, f.y};
            mma16816h(acc[0][ns], a_h[0], b);
            mma16816h(acc[0][ns], a_l[0], b);
            mma16816h(acc[1][ns], a_h[1], b);
            mma16816h(acc[1][ns], a_l[1], b);
        }
    }

    int gID = lane >> 2, tig = lane & 3;
    #pragma unroll
    for (int ms = 0; ms < 2; ms++) {
        int r0 = row0 + wm + ms * 16 + gID;
        #pragma unroll
        for (int ns = 0; ns < NS; ns++) {
            int col = (wnt + ns) * 8 + tig * 2;
            if (r0 < M) {
                __half2 p = __floats2half2_rn(acc[ms][ns][0], acc[ms][ns][1]);
                *(__half2*)(C + (size_t)r0 * N + col) = p;
            }
            if (r0 + 8 < M) {
                __half2 p = __floats2half2_rn(acc[ms][ns][2], acc[ms][ns][3]);
                *(__half2*)(C + (size_t)(r0 + 8) * N + col) = p;
            }
        }
    }
}

// ====================== gemm2: C[M,64] = A_fp16[M,128] @ W2, 1-term =========
__global__ void __launch_bounds__(256, 3) k_gemm2(
    const __half* __restrict__ A,
    const uint2* __restrict__ Wf,
    __half* __restrict__ C, int M) {
    const int N = 64, SP = 136, NS = 4, NT = 8;
    extern __shared__ __align__(16) __half sm[];
    __half* As = sm;                   // [128][SP]

    int tid = threadIdx.x, lane = tid & 31, wid = tid >> 5;
    int row0 = blockIdx.x * 128;

    #pragma unroll
    for (int i = tid; i < 2048; i += 256) {     // 2048 uint4 (8 halfs each)
        int r  = i >> 4;
        int c8 = (i & 15) << 3;
        int row = row0 + r;
        uint4 v = (row < M) ? *(const uint4*)(A + (size_t)row * 128 + c8)
                            : make_uint4(0u, 0u, 0u, 0u);
        *(uint4*)(As + r * SP + c8) = v;
    }
    __syncthreads();

    int wm  = (wid >> 1) * 32;
    int wnt = (wid & 1) * NS;

    float acc[2][NS][4];
    #pragma unroll
    for (int ms = 0; ms < 2; ms++)
        #pragma unroll
        for (int ns = 0; ns < NS; ns++)
            #pragma unroll
            for (int q = 0; q < 4; q++) acc[ms][ns][q] = 0.f;

    uint32_t base_a = smem_u32(As);

    #pragma unroll
    for (int k0 = 0; k0 < 128; k0 += 16) {
        int ks = k0 >> 4;
        uint32_t a[2][4];
        #pragma unroll
        for (int ms = 0; ms < 2; ms++) {
            int ar = wm + ms * 16 + (lane & 15);
            int ac = k0 + (lane >> 4) * 8;
            uint32_t off = (uint32_t)(ar * SP + ac) * 2;
            ldmx4(a[ms], base_a + off);
        }
        const uint2* fp = Wf + ((size_t)ks * NT + wnt) * 32 + lane;
        #pragma unroll
        for (int ns = 0; ns < NS; ns++) {
            uint2 f = __ldg(fp + ns * 32);
            uint32_t b[2] = {f.x, f.y};
            mma16816h(acc[0][ns], a[0], b);
            mma16816h(acc[1][ns], a[1], b);
        }
    }

    int gID = lane >> 2, tig = lane & 3;
    #pragma unroll
    for (int ms = 0; ms < 2; ms++) {
        int r0 = row0 + wm + ms * 16 + gID;
        #pragma unroll
        for (int ns = 0; ns < NS; ns++) {
            int col = (wnt + ns) * 8 + tig * 2;
            if (r0 < M) {
                __half2 p = __floats2half2_rn(acc[ms][ns][0], acc[ms][ns][1]);
                *(__half2*)(C + (size_t)r0 * N + col) = p;
            }
            if (r0 + 8 < M) {
                __half2 p = __floats2half2_rn(acc[ms][ns][2], acc[ms][ns][3]);
                *(__half2*)(C + (size_t)(r0 + 8) * N + col) = p;
            }
        }
    }
}

// ====================== aggregation: one warp per node, fp16 in/out ==========
template <int D, bool RELU>
__global__ void k_agg(const __half* __restrict__ h, const float* __restrict__ bias,
                      __half* __restrict__ zo) {
    int w    = (blockIdx.x * blockDim.x + threadIdx.x) >> 5;
    int lane = threadIdx.x & 31;
    if (w >= NN) return;
    const int V = D / 32;
    int beg = g_off[w], end = g_off[w + 1];
    float acc[V];
    #pragma unroll
    for (int i = 0; i < V; i++) acc[i] = 0.0f;

    for (int base = beg; base < end; base += 32) {
        int e = base + lane;
        int2 sn = (e < end) ? g_csrn[e] : make_int2(0, 0);
        int s = sn.x;
        float nm = __int_as_float(sn.y);
        int cnt = min(32, end - base);
        int j = 0;
        for (; j + 1 < cnt; j += 2) {
            int   s0 = __shfl_sync(0xffffffffu, s,  j);
            float n0 = __shfl_sync(0xffffffffu, nm, j);
            int   s1 = __shfl_sync(0xffffffffu, s,  j + 1);
            float n1 = __shfl_sync(0xffffffffu, nm, j + 1);
            const __half* p0 = h + (size_t)s0 * D + lane * V;
            const __half* p1 = h + (size_t)s1 * D + lane * V;
            if (V == 4) {
                uint2 u0 = *(const uint2*)p0;
                uint2 u1 = *(const uint2*)p1;
                float2 a0 = __half22float2(*(__half2*)&u0.x);
                float2 b0 = __half22float2(*(__half2*)&u0.y);
                float2 a1 = __half22float2(*(__half2*)&u1.x);
                float2 b1 = __half22float2(*(__half2*)&u1.y);
                acc[0] += a0.x * n0; acc[1] += a0.y * n0;
                acc[2] += b0.x * n0; acc[3] += b0.y * n0;
                acc[0] += a1.x * n1; acc[1] += a1.y * n1;
                acc[2] += b1.x * n1; acc[3] += b1.y * n1;
            } else {
                uint32_t u0 = *(const uint32_t*)p0;
                uint32_t u1 = *(const uint32_t*)p1;
                float2 a0 = __half22float2(*(__half2*)&u0);
                float2 a1 = __half22float2(*(__half2*)&u1);
                acc[0] += a0.x * n0; acc[1] += a0.y * n0;
                acc[0] += a1.x * n1; acc[1] += a1.y * n1;
            }
        }
        if (j < cnt) {
            int   s0 = __shfl_sync(0xffffffffu, s,  j);
            float n0 = __shfl_sync(0xffffffffu, nm, j);
            const __half* p0 = h + (size_t)s0 * D + lane * V;
            if (V == 4) {
                uint2 u0 = *(const uint2*)p0;
                float2 a0 = __half22float2(*(__half2*)&u0.x);
                float2 b0 = __half22float2(*(__half2*)&u0.y);
                acc[0] += a0.x * n0; acc[1] += a0.y * n0;
                acc[2] += b0.x * n0; acc[3] += b0.y * n0;
            } else {
                uint32_t u0 = *(const uint32_t*)p0;
                float2 a0 = __half22float2(*(__half2*)&u0);
                acc[0] += a0.x * n0; acc[1] += a0.y * n0;
            }
        }
    }

    float inv = g_invdeg[w];
    const __half* hp = h + (size_t)w * D + lane * V;
    const float* bp = bias + lane * V;
    __half* op = zo + (size_t)w * D + lane * V;
    if (V == 4) {
        uint2 su = *(const uint2*)hp;
        float2 s0 = __half22float2(*(__half2*)&su.x);
        float2 s1 = __half22float2(*(__half2*)&su.y);
        float4 bv = *(const float4*)bp;
        float ox = acc[0] + s0.x * inv + bv.x;
        float oy = acc[1] + s0.y * inv + bv.y;
        float oz = acc[2] + s1.x * inv + bv.z;
        float ow = acc[3] + s1.y * inv + bv.w;
        if (RELU) { ox = fmaxf(ox, 0.f); oy = fmaxf(oy, 0.f);
                    oz = fmaxf(oz, 0.f); ow = fmaxf(ow, 0.f); }
        uint2 ou;
        ou.x = packh2(ox, oy);
        ou.y = packh2(oz, ow);
        *(uint2*)op = ou;
    } else {
        uint32_t su = *(const uint32_t*)hp;
        float2 s0 = __half22float2(*(__half2*)&su);
        float2 bv = *(const float2*)bp;
        float ox = acc[0] + s0.x * inv + bv.x;
        float oy = acc[1] + s0.y * inv + bv.y;
        if (RELU) { ox = fmaxf(ox, 0.f); oy = fmaxf(oy, 0.f); }
        *(uint32_t*)op = packh2(ox, oy);
    }
}

// ====================== decode: fp16 z2, 16 lanes per edge ===================
__global__ void k_decode(const int* __restrict__ li, float* __restrict__ out) {
    int gid = blockIdx.x * blockDim.x + threadIdx.x;
    int e = gid >> 4;
    int l = gid & 15;
    if (e >= NL) return;
    int a = li[e];
    int b = li[NL + e];
    uint2 ua = *(const uint2*)(g_z2 + (size_t)a * DOUT + l * 4);
    uint2 ub = *(const uint2*)(g_z2 + (size_t)b * DOUT + l * 4);
    float2 a0 = __half22float2(*(__half2*)&ua.x);
    float2 a1 = __half22float2(*(__half2*)&ua.y);
    float2 b0 = __half22float2(*(__half2*)&ub.x);
    float2 b1 = __half22float2(*(__half2*)&ub.y);
    float d = a0.x * b0.x + a0.y * b0.y + a1.x * b1.x + a1.y * b1.y;
    d += __shfl_xor_sync(0xffffffffu, d, 1);
    d += __shfl_xor_sync(0xffffffffu, d, 2);
    d += __shfl_xor_sync(0xffffffffu, d, 4);
    d += __shfl_xor_sync(0xffffffffu, d, 8);
    if (l == 0) out[e] = d;
}

// ====================== launch ===============================================
extern "C" void kernel_launch(void* const* d_in, const int* in_sizes, int n_in,
                              void* d_out, int out_size) {
    const float* x   = (const float*)d_in[0];
    const int*   ei  = (const int*)d_in[1];
    const int*   eli = (const int*)d_in[2];
    const float* W1  = (const float*)d_in[3];
    const float* b1  = (const float*)d_in[4];
    const float* W2  = (const float*)d_in[5];
    const float* b2  = (const float*)d_in[6];
    float* out = (float*)d_out;

    __half *p_h1, *p_z, *p_h2, *p_z2;
    uint2 *p_wf1, *p_wf2;
    cudaGetSymbolAddress((void**)&p_h1, g_h1);
    cudaGetSymbolAddress((void**)&p_z,  g_z);
    cudaGetSymbolAddress((void**)&p_h2, g_h2);
    cudaGetSymbolAddress((void**)&p_z2, g_z2);
    cudaGetSymbolAddress((void**)&p_wf1, g_wf1);
    cudaGetSymbolAddress((void**)&p_wf2, g_wf2);

    const int SP = 136;
    const int SMEM1 = 2 * 128 * SP * 2;   // 69632 B (A hi/lo fp16)
    const int SMEM2 = 128 * SP * 2;       // 34816 B
    cudaFuncSetAttribute(k_gemm1, cudaFuncAttributeMaxDynamicSharedMemorySize, SMEM1);
    cudaFuncSetAttribute(k_gemm2, cudaFuncAttributeMaxDynamicSharedMemorySize, SMEM2);

    const int NB_NODE = (NN + 255) / 256;
    const int NB_EDGE = (NE + 255) / 256;
    const int NB_SCAN = (NN + 1023) / 1024;
    const int NB_GEMM = (NN + 127) / 128;
    const int NB_AGG  = (NN * 32 + 255) / 256;
    const int NB_DEC  = (NL * 16 + 255) / 256;

    // fork-join: setup branch on s2 overlaps W-prep + gemm1 on main stream.
    cudaStream_t s2;
    cudaStreamCreateWithFlags(&s2, cudaStreamNonBlocking);
    cudaEvent_t evF, evJ;
    cudaEventCreateWithFlags(&evF, cudaEventDisableTiming);
    cudaEventCreateWithFlags(&evJ, cudaEventDisableTiming);

    k_prepw<128><<<(8 * 16 * 32 + 255) / 256, 256>>>(W1, p_wf1);
    k_prepw<64><<<(8 * 8 * 32 + 255) / 256, 256>>>(W2, p_wf2);

    cudaEventRecord(evF, 0);
    cudaStreamWaitEvent(s2, evF, 0);

    k_zero_deg<<<NB_NODE, 256, 0, s2>>>();
    k_gemm1<<<NB_GEMM, 256, SMEM1>>>(x, p_wf1, p_h1, NN);      // 4th launch (profiled)
    k_degree<<<NB_EDGE, 256, 0, s2>>>(ei);
    k_scan1<<<NB_SCAN, 1024, 0, s2>>>(NN);
    k_scan2<<<1, 128, 0, s2>>>(NB_SCAN);
    k_scan3<<<NB_SCAN, 1024, 0, s2>>>(NN);
    k_scatter<<<NB_EDGE, 256, 0, s2>>>(ei);

    cudaEventRecord(evJ, s2);
    cudaStreamWaitEvent(0, evJ, 0);

    k_agg<DH, true><<<NB_AGG, 256>>>(p_h1, b1, p_z);           // z = relu(Ah1+b1) fp16
    k_gemm2<<<NB_GEMM, 256, SMEM2>>>(p_z, p_wf2, p_h2, NN);    // h2 = z @ W2 fp16
    k_agg<DOUT, false><<<NB_AGG, 256>>>(p_h2, b2, p_z2);       // z2 = Ah2+b2 fp16
    k_decode<<<NB_DEC, 256>>>(eli, out);
}

// round 8
// speedup vs baseline: 1.8594x; 1.0113x over previous
#include <cuda_runtime.h>
#include <cuda_fp16.h>
#include <cstdint>

#define NN 100000
#define NE 1600000
#define NL 200000
#define DH  128
#define DOUT 64

// ====================== scratch (device globals) =============================
__device__ __align__(16) int   g_deg[NN];
__device__ __align__(16) float g_dinv[NN];
__device__ __align__(16) float g_invdeg[NN];
__device__ __align__(16) int   g_off[NN + 1];
__device__ __align__(16) int   g_cursor[NN];
__device__ __align__(16) int2  g_csrn[NE];               // {src, norm bits}
__device__ __align__(16) int   g_bsum[128];
__device__ __align__(16) __half g_h1[(size_t)NN * DH];
__device__ __align__(16) __half g_z [(size_t)NN * DH];
__device__ __align__(16) __half g_h2[(size_t)NN * DOUT];
__device__ __align__(16) __half g_z2[(size_t)NN * DOUT];
// W fragments (fp16), mma-ready: [ks][ntile][lane] -> uint2{b0,b1}
__device__ __align__(16) uint2 g_wf1[8 * 16 * 32];
__device__ __align__(16) uint2 g_wf2[8 * 8 * 32];

// ====================== small helpers ========================================
__device__ __forceinline__ uint32_t smem_u32(const void* p) {
    uint32_t a;
    asm("{ .reg .u64 t; cvta.to.shared.u64 t, %1; cvt.u32.u64 %0, t; }" : "=r"(a) : "l"(p));
    return a;
}
__device__ __forceinline__ void ldmx4(uint32_t* r, uint32_t addr) {
    asm volatile("ldmatrix.sync.aligned.m8n8.x4.shared.b16 {%0,%1,%2,%3}, [%4];"
                 : "=r"(r[0]), "=r"(r[1]), "=r"(r[2]), "=r"(r[3]) : "r"(addr));
}
__device__ __forceinline__ void mma16816h(float* c, const uint32_t* a, const uint32_t* b) {
    asm volatile(
        "mma.sync.aligned.m16n8k16.row.col.f32.f16.f16.f32 "
        "{%0,%1,%2,%3}, {%4,%5,%6,%7}, {%8,%9}, {%0,%1,%2,%3};"
        : "+f"(c[0]), "+f"(c[1]), "+f"(c[2]), "+f"(c[3])
        : "r"(a[0]), "r"(a[1]), "r"(a[2]), "r"(a[3]), "r"(b[0]), "r"(b[1]));
}
__device__ __forceinline__ uint32_t packh2(float a, float b) {
    __half2 p = __floats2half2_rn(a, b);
    return *(uint32_t*)&p;
}

// ====================== setup kernels ========================================
__global__ void k_zero_deg() {
    int i = blockIdx.x * blockDim.x + threadIdx.x;
    if (i < NN) g_deg[i] = 0;
}
__global__ void k_degree(const int* __restrict__ ei) {
    int e = blockIdx.x * blockDim.x + threadIdx.x;
    if (e < NE) atomicAdd(&g_deg[ei[NE + e]], 1);
}
__global__ void k_scan1(int n) {
    __shared__ int wsum[32];
    int t = threadIdx.x;
    int gid = blockIdx.x * 1024 + t;
    int v = (gid < n) ? g_deg[gid] : 0;
    if (gid < n) {
        float d = (float)(v + 1);
        g_dinv[gid]   = rsqrtf(d);
        g_invdeg[gid] = 1.0f / d;
    }
    int x = v;
    #pragma unroll
    for (int o = 1; o < 32; o <<= 1) {
        int y = __shfl_up_sync(0xffffffffu, x, o);
        if ((t & 31) >= o) x += y;
    }
    if ((t & 31) == 31) wsum[t >> 5] = x;
    __syncthreads();
    if (t < 32) {
        int w = wsum[t];
        int xx = w;
        #pragma unroll
        for (int o = 1; o < 32; o <<= 1) {
            int y = __shfl_up_sync(0xffffffffu, xx, o);
            if (t >= o) xx += y;
        }
        wsum[t] = xx - w;
    }
    __syncthreads();
    int excl = x - v + wsum[t >> 5];
    if (gid < n) g_off[gid] = excl;
    if (t == 1023) g_bsum[blockIdx.x] = excl + v;
}
__global__ void k_scan2(int nb) {
    __shared__ int s[128];
    int t = threadIdx.x;
    int v = (t < nb) ? g_bsum[t] : 0;
    s[t] = v;
    __syncthreads();
    for (int o = 1; o < 128; o <<= 1) {
        int x = (t >= o) ? s[t - o] : 0;
        __syncthreads();
        s[t] += x;
        __syncthreads();
    }
    if (t < nb) g_bsum[t] = s[t] - v;
}
__global__ void k_scan3(int n) {
    int t = threadIdx.x;
    int gid = blockIdx.x * 1024 + t;
    if (gid < n) {
        int v = g_off[gid] + g_bsum[blockIdx.x];
        g_off[gid]    = v;
        g_cursor[gid] = v;
    }
    if (gid == 0) g_off[n] = NE;
}
__global__ void k_scatter(const int* __restrict__ ei) {
    int e = blockIdx.x * blockDim.x + threadIdx.x;
    if (e < NE) {
        int s = ei[e];
        int d = ei[NE + e];
        float nm = g_dinv[s] * g_dinv[d];
        int p = atomicAdd(&g_cursor[d], 1);
        g_csrn[p] = make_int2(s, __float_as_int(nm));
    }
}

// ====================== W prep: fp16 fragment-major ==========================
template <int N>
__global__ void k_prepw(const float* __restrict__ W, uint2* __restrict__ frag) {
    int idx = blockIdx.x * blockDim.x + threadIdx.x;
    const int NT = N / 8;
    if (idx >= 8 * NT * 32) return;
    int lane = idx & 31;
    int nt   = (idx >> 5) % NT;
    int ks   = idx / (32 * NT);
    int n = nt * 8 + (lane >> 2);
    int k = ks * 16 + (lane & 3) * 2;
    uint2 o;
    o.x = packh2(W[(k    ) * N + n], W[(k + 1) * N + n]);
    o.y = packh2(W[(k + 8) * N + n], W[(k + 9) * N + n]);
    frag[idx] = o;
}

// ====================== gemm1: C[M,128] = A_fp32[M,128] @ W1, 2-term fp16 ====
// CTA tile 64 x 128, 8 warps 2(m) x 4(n), warp = 32 x 32. 3 CTAs/SM.
__global__ void __launch_bounds__(256, 3) k_gemm1(
    const float* __restrict__ A,
    const uint2* __restrict__ Wf,
    __half* __restrict__ C, int M) {
    const int N = 128, SP = 136, NS = 4, NT = 16;
    extern __shared__ __align__(16) __half sm[];
    __half* As_h = sm;                 // [64][SP]
    __half* As_l = sm + 64 * SP;

    int tid = threadIdx.x, lane = tid & 31, wid = tid >> 5;
    int row0 = blockIdx.x * 64;

    #pragma unroll
    for (int i = tid; i < 2048; i += 256) {     // 64 rows x 32 float4
        int r  = i >> 5;
        int c4 = (i & 31) << 2;
        int row = row0 + r;
        float4 v = (row < M) ? *(const float4*)(A + (size_t)row * 128 + c4)
                             : make_float4(0.f, 0.f, 0.f, 0.f);
        __half h0 = __float2half_rn(v.x), h1 = __float2half_rn(v.y);
        __half h2 = __float2half_rn(v.z), h3 = __float2half_rn(v.w);
        uint32_t hp0, hp1;
        { __half2 p = __halves2half2(h0, h1); hp0 = *(uint32_t*)&p; }
        { __half2 p = __halves2half2(h2, h3); hp1 = *(uint32_t*)&p; }
        uint32_t lp0 = packh2(v.x - __half2float(h0), v.y - __half2float(h1));
        uint32_t lp1 = packh2(v.z - __half2float(h2), v.w - __half2float(h3));
        int o = r * SP + c4;
        *(uint2*)(As_h + o) = make_uint2(hp0, hp1);
        *(uint2*)(As_l + o) = make_uint2(lp0, lp1);
    }
    __syncthreads();

    int wm  = (wid >> 2) * 32;          // 2 m-groups
    int wnt = (wid & 3) * NS;           // 4 n-groups x 4 tiles

    float acc[2][NS][4];
    #pragma unroll
    for (int ms = 0; ms < 2; ms++)
        #pragma unroll
        for (int ns = 0; ns < NS; ns++)
            #pragma unroll
            for (int q = 0; q < 4; q++) acc[ms][ns][q] = 0.f;

    uint32_t base_ah = smem_u32(As_h);
    uint32_t base_al = smem_u32(As_l);

    #pragma unroll
    for (int k0 = 0; k0 < 128; k0 += 16) {
        int ks = k0 >> 4;
        uint32_t a_h[2][4], a_l[2][4];
        #pragma unroll
        for (int ms = 0; ms < 2; ms++) {
            int ar = wm + ms * 16 + (lane & 15);
            int ac = k0 + (lane >> 4) * 8;
            uint32_t off = (uint32_t)(ar * SP + ac) * 2;
            ldmx4(a_h[ms], base_ah + off);
            ldmx4(a_l[ms], base_al + off);
        }
        const uint2* fp = Wf + ((size_t)ks * NT + wnt) * 32 + lane;
        #pragma unroll
        for (int ns = 0; ns < NS; ns++) {
            uint2 f = __ldg(fp + ns * 32);
            uint32_t b[2] = {f.x, f.y};
            mma16816h(acc[0][ns], a_h[0], b);
            mma16816h(acc[0][ns], a_l[0], b);
            mma16816h(acc[1][ns], a_h[1], b);
            mma16816h(acc[1][ns], a_l[1], b);
        }
    }

    int gID = lane >> 2, tig = lane & 3;
    #pragma unroll
    for (int ms = 0; ms < 2; ms++) {
        int r0 = row0 + wm + ms * 16 + gID;
        #pragma unroll
        for (int ns = 0; ns < NS; ns++) {
            int col = (wnt + ns) * 8 + tig * 2;
            if (r0 < M) {
                __half2 p = __floats2half2_rn(acc[ms][ns][0], acc[ms][ns][1]);
                *(__half2*)(C + (size_t)r0 * N + col) = p;
            }
            if (r0 + 8 < M) {
                __half2 p = __floats2half2_rn(acc[ms][ns][2], acc[ms][ns][3]);
                *(__half2*)(C + (size_t)(r0 + 8) * N + col) = p;
            }
        }
    }
}

// ====================== gemm2: C[M,64] = A_fp16[M,128] @ W2, 1-term =========
__global__ void __launch_bounds__(256, 3) k_gemm2(
    const __half* __restrict__ A,
    const uint2* __restrict__ Wf,
    __half* __restrict__ C, int M) {
    const int N = 64, SP = 136, NS = 4, NT = 8;
    extern __shared__ __align__(16) __half sm[];
    __half* As = sm;                   // [128][SP]

    int tid = threadIdx.x, lane = tid & 31, wid = tid >> 5;
    int row0 = blockIdx.x * 128;

    #pragma unroll
    for (int i = tid; i < 2048; i += 256) {
        int r  = i >> 4;
        int c8 = (i & 15) << 3;
        int row = row0 + r;
        uint4 v = (row < M) ? *(const uint4*)(A + (size_t)row * 128 + c8)
                            : make_uint4(0u, 0u, 0u, 0u);
        *(uint4*)(As + r * SP + c8) = v;
    }
    __syncthreads();

    int wm  = (wid >> 1) * 32;
    int wnt = (wid & 1) * NS;

    float acc[2][NS][4];
    #pragma unroll
    for (int ms = 0; ms < 2; ms++)
        #pragma unroll
        for (int ns = 0; ns < NS; ns++)
            #pragma unroll
            for (int q = 0; q < 4; q++) acc[ms][ns][q] = 0.f;

    uint32_t base_a = smem_u32(As);

    #pragma unroll
    for (int k0 = 0; k0 < 128; k0 += 16) {
        int ks = k0 >> 4;
        uint32_t a[2][4];
        #pragma unroll
        for (int ms = 0; ms < 2; ms++) {
            int ar = wm + ms * 16 + (lane & 15);
            int ac = k0 + (lane >> 4) * 8;
            uint32_t off = (uint32_t)(ar * SP + ac) * 2;
            ldmx4(a[ms], base_a + off);
        }
        const uint2* fp = Wf + ((size_t)ks * NT + wnt) * 32 + lane;
        #pragma unroll
        for (int ns = 0; ns < NS; ns++) {
            uint2 f = __ldg(fp + ns * 32);
            uint32_t b[2] = {f.x, f.y};
            mma16816h(acc[0][ns], a[0], b);
            mma16816h(acc[1][ns], a[1], b);
        }
    }

    int gID = lane >> 2, tig = lane & 3;
    #pragma unroll
    for (int ms = 0; ms < 2; ms++) {
        int r0 = row0 + wm + ms * 16 + gID;
        #pragma unroll
        for (int ns = 0; ns < NS; ns++) {
            int col = (wnt + ns) * 8 + tig * 2;
            if (r0 < M) {
                __half2 p = __floats2half2_rn(acc[ms][ns][0], acc[ms][ns][1]);
                *(__half2*)(C + (size_t)r0 * N + col) = p;
            }
            if (r0 + 8 < M) {
                __half2 p = __floats2half2_rn(acc[ms][ns][2], acc[ms][ns][3]);
                *(__half2*)(C + (size_t)(r0 + 8) * N + col) = p;
            }
        }
    }
}

// ====================== aggregation: one warp per node, fp16 in/out ==========
template <int D, bool RELU>
__global__ void k_agg(const __half* __restrict__ h, const float* __restrict__ bias,
                      __half* __restrict__ zo) {
    int w    = (blockIdx.x * blockDim.x + threadIdx.x) >> 5;
    int lane = threadIdx.x & 31;
    if (w >= NN) return;
    const int V = D / 32;
    int beg = g_off[w], end = g_off[w + 1];
    float acc[V];
    #pragma unroll
    for (int i = 0; i < V; i++) acc[i] = 0.0f;

    for (int base = beg; base < end; base += 32) {
        int e = base + lane;
        int2 sn = (e < end) ? g_csrn[e] : make_int2(0, 0);
        int s = sn.x;
        float nm = __int_as_float(sn.y);
        int cnt = min(32, end - base);
        int j = 0;
        for (; j + 1 < cnt; j += 2) {
            int   s0 = __shfl_sync(0xffffffffu, s,  j);
            float n0 = __shfl_sync(0xffffffffu, nm, j);
            int   s1 = __shfl_sync(0xffffffffu, s,  j + 1);
            float n1 = __shfl_sync(0xffffffffu, nm, j + 1);
            const __half* p0 = h + (size_t)s0 * D + lane * V;
            const __half* p1 = h + (size_t)s1 * D + lane * V;
            if (V == 4) {
                uint2 u0 = *(const uint2*)p0;
                uint2 u1 = *(const uint2*)p1;
                float2 a0 = __half22float2(*(__half2*)&u0.x);
                float2 b0 = __half22float2(*(__half2*)&u0.y);
                float2 a1 = __half22float2(*(__half2*)&u1.x);
                float2 b1 = __half22float2(*(__half2*)&u1.y);
                acc[0] += a0.x * n0; acc[1] += a0.y * n0;
                acc[2] += b0.x * n0; acc[3] += b0.y * n0;
                acc[0] += a1.x * n1; acc[1] += a1.y * n1;
                acc[2] += b1.x * n1; acc[3] += b1.y * n1;
            } else {
                uint32_t u0 = *(const uint32_t*)p0;
                uint32_t u1 = *(const uint32_t*)p1;
                float2 a0 = __half22float2(*(__half2*)&u0);
                float2 a1 = __half22float2(*(__half2*)&u1);
                acc[0] += a0.x * n0; acc[1] += a0.y * n0;
                acc[0] += a1.x * n1; acc[1] += a1.y * n1;
            }
        }
        if (j < cnt) {
            int   s0 = __shfl_sync(0xffffffffu, s,  j);
            float n0 = __shfl_sync(0xffffffffu, nm, j);
            const __half* p0 = h + (size_t)s0 * D + lane * V;
            if (V == 4) {
                uint2 u0 = *(const uint2*)p0;
                float2 a0 = __half22float2(*(__half2*)&u0.x);
                float2 b0 = __half22float2(*(__half2*)&u0.y);
                acc[0] += a0.x * n0; acc[1] += a0.y * n0;
                acc[2] += b0.x * n0; acc[3] += b0.y * n0;
            } else {
                uint32_t u0 = *(const uint32_t*)p0;
                float2 a0 = __half22float2(*(__half2*)&u0);
                acc[0] += a0.x * n0; acc[1] += a0.y * n0;
            }
        }
    }

    float inv = g_invdeg[w];
    const __half* hp = h + (size_t)w * D + lane * V;
    const float* bp = bias + lane * V;
    __half* op = zo + (size_t)w * D + lane * V;
    if (V == 4) {
        uint2 su = *(const uint2*)hp;
        float2 s0 = __half22float2(*(__half2*)&su.x);
        float2 s1 = __half22float2(*(__half2*)&su.y);
        float4 bv = *(const float4*)bp;
        float ox = acc[0] + s0.x * inv + bv.x;
        float oy = acc[1] + s0.y * inv + bv.y;
        float oz = acc[2] + s1.x * inv + bv.z;
        float ow = acc[3] + s1.y * inv + bv.w;
        if (RELU) { ox = fmaxf(ox, 0.f); oy = fmaxf(oy, 0.f);
                    oz = fmaxf(oz, 0.f); ow = fmaxf(ow, 0.f); }
        uint2 ou;
        ou.x = packh2(ox, oy);
        ou.y = packh2(oz, ow);
        *(uint2*)op = ou;
    } else {
        uint32_t su = *(const uint32_t*)hp;
        float2 s0 = __half22float2(*(__half2*)&su);
        float2 bv = *(const float2*)bp;
        float ox = acc[0] + s0.x * inv + bv.x;
        float oy = acc[1] + s0.y * inv + bv.y;
        if (RELU) { ox = fmaxf(ox, 0.f); oy = fmaxf(oy, 0.f); }
        *(uint32_t*)op = packh2(ox, oy);
    }
}

// ====================== decode: fp16 z2, 16 lanes per edge ===================
__global__ void k_decode(const int* __restrict__ li, float* __restrict__ out) {
    int gid = blockIdx.x * blockDim.x + threadIdx.x;
    int e = gid >> 4;
    int l = gid & 15;
    if (e >= NL) return;
    int a = li[e];
    int b = li[NL + e];
    uint2 ua = *(const uint2*)(g_z2 + (size_t)a * DOUT + l * 4);
    uint2 ub = *(const uint2*)(g_z2 + (size_t)b * DOUT + l * 4);
    float2 a0 = __half22float2(*(__half2*)&ua.x);
    float2 a1 = __half22float2(*(__half2*)&ua.y);
    float2 b0 = __half22float2(*(__half2*)&ub.x);
    float2 b1 = __half22float2(*(__half2*)&ub.y);
    float d = a0.x * b0.x + a0.y * b0.y + a1.x * b1.x + a1.y * b1.y;
    d += __shfl_xor_sync(0xffffffffu, d, 1);
    d += __shfl_xor_sync(0xffffffffu, d, 2);
    d += __shfl_xor_sync(0xffffffffu, d, 4);
    d += __shfl_xor_sync(0xffffffffu, d, 8);
    if (l == 0) out[e] = d;
}

// ====================== launch ===============================================
extern "C" void kernel_launch(void* const* d_in, const int* in_sizes, int n_in,
                              void* d_out, int out_size) {
    const float* x   = (const float*)d_in[0];
    const int*   ei  = (const int*)d_in[1];
    const int*   eli = (const int*)d_in[2];
    const float* W1  = (const float*)d_in[3];
    const float* b1  = (const float*)d_in[4];
    const float* W2  = (const float*)d_in[5];
    const float* b2  = (const float*)d_in[6];
    float* out = (float*)d_out;

    __half *p_h1, *p_z, *p_h2, *p_z2;
    uint2 *p_wf1, *p_wf2;
    cudaGetSymbolAddress((void**)&p_h1, g_h1);
    cudaGetSymbolAddress((void**)&p_z,  g_z);
    cudaGetSymbolAddress((void**)&p_h2, g_h2);
    cudaGetSymbolAddress((void**)&p_z2, g_z2);
    cudaGetSymbolAddress((void**)&p_wf1, g_wf1);
    cudaGetSymbolAddress((void**)&p_wf2, g_wf2);

    const int SP = 136;
    const int SMEM1 = 2 * 64 * SP * 2;    // 34816 B (64-row A hi/lo fp16)
    const int SMEM2 = 128 * SP * 2;       // 34816 B
    cudaFuncSetAttribute(k_gemm1, cudaFuncAttributeMaxDynamicSharedMemorySize, SMEM1);
    cudaFuncSetAttribute(k_gemm2, cudaFuncAttributeMaxDynamicSharedMemorySize, SMEM2);

    const int NB_NODE  = (NN + 255) / 256;
    const int NB_EDGE  = (NE + 255) / 256;
    const int NB_SCAN  = (NN + 1023) / 1024;
    const int NB_GEMM1 = (NN + 63) / 64;     // 1563
    const int NB_GEMM2 = (NN + 127) / 128;   // 782
    const int NB_AGG   = (NN * 32 + 255) / 256;
    const int NB_DEC   = (NL * 16 + 255) / 256;

    // fork-join: setup branch on s2 overlaps W-prep + gemm1 on main stream.
    cudaStream_t s2;
    cudaStreamCreateWithFlags(&s2, cudaStreamNonBlocking);
    cudaEvent_t evF, evJ;
    cudaEventCreateWithFlags(&evF, cudaEventDisableTiming);
    cudaEventCreateWithFlags(&evJ, cudaEventDisableTiming);

    k_prepw<128><<<(8 * 16 * 32 + 255) / 256, 256>>>(W1, p_wf1);
    k_prepw<64><<<(8 * 8 * 32 + 255) / 256, 256>>>(W2, p_wf2);

    cudaEventRecord(evF, 0);
    cudaStreamWaitEvent(s2, evF, 0);

    k_zero_deg<<<NB_NODE, 256, 0, s2>>>();
    k_gemm1<<<NB_GEMM1, 256, SMEM1>>>(x, p_wf1, p_h1, NN);     // 4th launch (profiled)
    k_degree<<<NB_EDGE, 256, 0, s2>>>(ei);
    k_scan1<<<NB_SCAN, 1024, 0, s2>>>(NN);
    k_scan2<<<1, 128, 0, s2>>>(NB_SCAN);
    k_scan3<<<NB_SCAN, 1024, 0, s2>>>(NN);
    k_scatter<<<NB_EDGE, 256, 0, s2>>>(ei);

    cudaEventRecord(evJ, s2);
    cudaStreamWaitEvent(0, evJ, 0);

    k_agg<DH, true><<<NB_AGG, 256>>>(p_h1, b1, p_z);           // z = relu(Ah1+b1) fp16
    k_gemm2<<<NB_GEMM2, 256, SMEM2>>>(p_z, p_wf2, p_h2, NN);   // h2 = z @ W2 fp16
    k_agg<DOUT, false><<<NB_AGG, 256>>>(p_h2, b2, p_z2);       // z2 = Ah2+b2 fp16
    k_decode<<<NB_DEC, 256>>>(eli, out);
}